// round 3
// baseline (speedup 1.0000x reference)
#include <cuda_runtime.h>
#include <cuda_bf16.h>
#include <math.h>

// ---------------------------------------------------------------------------
// Problem constants (shapes fixed by the reference)
// ---------------------------------------------------------------------------
#define HID    512
#define GATES  2048      // 4*HID
#define MAXLEN 128
#define BMAX   1024
#define TMAX   (BMAX * 127)   // 130048 max ragged tokens

// ---------------------------------------------------------------------------
// Scratch (static __device__ arrays; no allocation allowed)
// ---------------------------------------------------------------------------
__device__ float g_x1[(size_t)TMAX * HID];        // encoder layer 0 out
__device__ float g_x2[(size_t)TMAX * HID];        // encoder layer 1 out
__device__ float g_xproj[(size_t)TMAX * GATES];   // x @ Wih^T  (no bias)
__device__ float g_h0[BMAX * HID];
__device__ float g_h1[BMAX * HID];
__device__ float g_c [BMAX * HID];
__device__ float g_t0[BMAX * HID];
__device__ float g_t1[BMAX * HID];
__device__ int   g_starts[BMAX];

// ---------------------------------------------------------------------------
// starts[b] = exclusive prefix sum of segment sizes
// ---------------------------------------------------------------------------
__global__ void scan_starts_kernel(const int* __restrict__ sizes, int* __restrict__ starts, int B) {
    __shared__ int s[BMAX];
    int tid = threadIdx.x;
    if (tid < B) s[tid] = sizes[tid];
    __syncthreads();
    if (tid == 0) {
        int acc = 0;
        for (int i = 0; i < B; i++) { starts[i] = acc; acc += s[i]; }
    }
}

__global__ void fill_zero_kernel(float* __restrict__ p, int n) {
    int i = blockIdx.x * blockDim.x + threadIdx.x;
    if (i < n) p[i] = 0.f;
}

// ---------------------------------------------------------------------------
// Generic NT GEMM:  C[M,N] = act( A[M,K] @ B[N,K]^T + bias[N] ) (+ R[M,N])
//   mode 0: none     mode 1: relu     mode 2: relu + residual R
// Tiles: 64x64x16, 256 threads, 4x4 micro-tile per thread.
// ---------------------------------------------------------------------------
#define BM 64
#define BN 64
#define BK 16

__global__ __launch_bounds__(256) void gemm_nt_kernel(
    const float* __restrict__ A, const float* __restrict__ B,
    const float* __restrict__ bias, const float* __restrict__ R,
    float* __restrict__ C, int M, int N, int K, int mode)
{
    __shared__ float As[BK][BM];
    __shared__ float Bs[BK][BN];

    const int m0 = blockIdx.y * BM;
    const int n0 = blockIdx.x * BN;
    const int tid = threadIdx.x;
    const int tx = tid & 15;        // 0..15
    const int ty = tid >> 4;        // 0..15
    const int lrow = tid >> 2;      // 0..63
    const int lkq  = (tid & 3) * 4; // 0,4,8,12

    float acc[4][4] = {};

    for (int k0 = 0; k0 < K; k0 += BK) {
        // --- load A tile (transposed into smem) ---
        {
            float4 v = make_float4(0.f, 0.f, 0.f, 0.f);
            int gm = m0 + lrow;
            int gk = k0 + lkq;
            if (gm < M) {
                if (gk + 3 < K) {
                    v = *reinterpret_cast<const float4*>(A + (size_t)gm * K + gk);
                } else {
                    float t[4] = {0.f, 0.f, 0.f, 0.f};
                    #pragma unroll
                    for (int q = 0; q < 4; q++) if (gk + q < K) t[q] = A[(size_t)gm * K + gk + q];
                    v = make_float4(t[0], t[1], t[2], t[3]);
                }
            }
            As[lkq + 0][lrow] = v.x; As[lkq + 1][lrow] = v.y;
            As[lkq + 2][lrow] = v.z; As[lkq + 3][lrow] = v.w;
        }
        // --- load B tile ---
        {
            float4 v = make_float4(0.f, 0.f, 0.f, 0.f);
            int gn = n0 + lrow;
            int gk = k0 + lkq;
            if (gn < N) {
                if (gk + 3 < K) {
                    v = *reinterpret_cast<const float4*>(B + (size_t)gn * K + gk);
                } else {
                    float t[4] = {0.f, 0.f, 0.f, 0.f};
                    #pragma unroll
                    for (int q = 0; q < 4; q++) if (gk + q < K) t[q] = B[(size_t)gn * K + gk + q];
                    v = make_float4(t[0], t[1], t[2], t[3]);
                }
            }
            Bs[lkq + 0][lrow] = v.x; Bs[lkq + 1][lrow] = v.y;
            Bs[lkq + 2][lrow] = v.z; Bs[lkq + 3][lrow] = v.w;
        }
        __syncthreads();

        #pragma unroll
        for (int k = 0; k < BK; k++) {
            float4 a = *reinterpret_cast<const float4*>(&As[k][ty * 4]);
            float4 b = *reinterpret_cast<const float4*>(&Bs[k][tx * 4]);
            acc[0][0] += a.x * b.x; acc[0][1] += a.x * b.y; acc[0][2] += a.x * b.z; acc[0][3] += a.x * b.w;
            acc[1][0] += a.y * b.x; acc[1][1] += a.y * b.y; acc[1][2] += a.y * b.z; acc[1][3] += a.y * b.w;
            acc[2][0] += a.z * b.x; acc[2][1] += a.z * b.y; acc[2][2] += a.z * b.z; acc[2][3] += a.z * b.w;
            acc[3][0] += a.w * b.x; acc[3][1] += a.w * b.y; acc[3][2] += a.w * b.z; acc[3][3] += a.w * b.w;
        }
        __syncthreads();
    }

    #pragma unroll
    for (int i = 0; i < 4; i++) {
        int gm = m0 + ty * 4 + i;
        if (gm >= M) continue;
        #pragma unroll
        for (int j = 0; j < 4; j++) {
            int gn = n0 + tx * 4 + j;
            if (gn >= N) continue;
            float v = acc[i][j];
            if (bias) v += bias[gn];
            if (mode >= 1) v = fmaxf(v, 0.f);
            if (mode == 2) v += R[(size_t)gm * N + gn];
            C[(size_t)gm * N + gn] = v;
        }
    }
}

// ---------------------------------------------------------------------------
// Fused LSTM step: gates = h_prev @ Whh^T + (bih+bhh) + gather(xproj), then
// elementwise c/h update. CTA tile: 64 batch rows x (16 hidden x 4 gates).
// Local B column c maps to gate=(c&3), hid = nb*16 + (c>>2), so each thread's
// 4 accumulator columns are the i/f/g/o of one hidden unit.
// ---------------------------------------------------------------------------
__global__ __launch_bounds__(256) void lstm_step_kernel(
    const float* __restrict__ Hprev, float* __restrict__ Hnext,
    float* __restrict__ Cst,
    const float* __restrict__ Whh,
    const float* __restrict__ bih, const float* __restrict__ bhh,
    const float* __restrict__ xproj,
    const int* __restrict__ starts, const int* __restrict__ sizes,
    int t, int B)
{
    __shared__ float As[BK][BM];
    __shared__ float Bs[BK][BN];

    const int nb = blockIdx.x;        // hidden slice: 16 units
    const int m0 = blockIdx.y * BM;
    const int tid = threadIdx.x;
    const int tx = tid & 15;
    const int ty = tid >> 4;
    const int lrow = tid >> 2;        // local B col / A row 0..63
    const int lkq  = (tid & 3) * 4;

    // Whh row for local column lrow
    const int brow = (lrow & 3) * HID + nb * 16 + (lrow >> 2);

    float acc[4][4] = {};

    for (int k0 = 0; k0 < HID; k0 += BK) {
        {
            int gm = m0 + lrow;
            float4 v = make_float4(0.f, 0.f, 0.f, 0.f);
            if (gm < B) v = *reinterpret_cast<const float4*>(Hprev + (size_t)gm * HID + k0 + lkq);
            As[lkq + 0][lrow] = v.x; As[lkq + 1][lrow] = v.y;
            As[lkq + 2][lrow] = v.z; As[lkq + 3][lrow] = v.w;
        }
        {
            float4 v = *reinterpret_cast<const float4*>(Whh + (size_t)brow * HID + k0 + lkq);
            Bs[lkq + 0][lrow] = v.x; Bs[lkq + 1][lrow] = v.y;
            Bs[lkq + 2][lrow] = v.z; Bs[lkq + 3][lrow] = v.w;
        }
        __syncthreads();

        #pragma unroll
        for (int k = 0; k < BK; k++) {
            float4 a = *reinterpret_cast<const float4*>(&As[k][ty * 4]);
            float4 b = *reinterpret_cast<const float4*>(&Bs[k][tx * 4]);
            acc[0][0] += a.x * b.x; acc[0][1] += a.x * b.y; acc[0][2] += a.x * b.z; acc[0][3] += a.x * b.w;
            acc[1][0] += a.y * b.x; acc[1][1] += a.y * b.y; acc[1][2] += a.y * b.z; acc[1][3] += a.y * b.w;
            acc[2][0] += a.z * b.x; acc[2][1] += a.z * b.y; acc[2][2] += a.z * b.z; acc[2][3] += a.z * b.w;
            acc[3][0] += a.w * b.x; acc[3][1] += a.w * b.y; acc[3][2] += a.w * b.z; acc[3][3] += a.w * b.w;
        }
        __syncthreads();
    }

    const int hid = nb * 16 + tx;
    const float bI = bih[0 * HID + hid] + bhh[0 * HID + hid];
    const float bF = bih[1 * HID + hid] + bhh[1 * HID + hid];
    const float bG = bih[2 * HID + hid] + bhh[2 * HID + hid];
    const float bO = bih[3 * HID + hid] + bhh[3 * HID + hid];

    #pragma unroll
    for (int i = 0; i < 4; i++) {
        int b = m0 + ty * 4 + i;
        if (b >= B) continue;
        float gi = acc[i][0] + bI;
        float gf = acc[i][1] + bF;
        float gg = acc[i][2] + bG;
        float go = acc[i][3] + bO;
        int sz = sizes[b];
        if (t < sz) {
            size_t base = (size_t)(starts[b] + t) * GATES;
            gi += xproj[base + 0 * HID + hid];
            gf += xproj[base + 1 * HID + hid];
            gg += xproj[base + 2 * HID + hid];
            go += xproj[base + 3 * HID + hid];
        }
        size_t idx = (size_t)b * HID + hid;
        float cold = Cst[idx];
        float is = 1.f / (1.f + expf(-gi));
        float fs = 1.f / (1.f + expf(-gf));
        float gt = tanhf(gg);
        float os = 1.f / (1.f + expf(-go));
        float cn = fs * cold + is * gt;
        Cst[idx] = cn;
        Hnext[idx] = os * tanhf(cn);
    }
}

// ---------------------------------------------------------------------------
// Decoder: out[b] = dot(X[b,:], Wd) + bd   (warp per row)
// ---------------------------------------------------------------------------
__global__ void decoder_kernel(const float* __restrict__ X, const float* __restrict__ Wd,
                               const float* __restrict__ bd, float* __restrict__ out, int B)
{
    int warp = (blockIdx.x * blockDim.x + threadIdx.x) >> 5;
    int lane = threadIdx.x & 31;
    if (warp >= B) return;
    const float4* row = reinterpret_cast<const float4*>(X + (size_t)warp * HID);
    const float4* w   = reinterpret_cast<const float4*>(Wd);
    float s = 0.f;
    #pragma unroll
    for (int i = lane; i < HID / 4; i += 32) {
        float4 a = row[i], bw = w[i];
        s += a.x * bw.x + a.y * bw.y + a.z * bw.z + a.w * bw.w;
    }
    #pragma unroll
    for (int o = 16; o > 0; o >>= 1) s += __shfl_down_sync(0xffffffffu, s, o);
    if (lane == 0) out[warp] = s + bd[0];
}

// ---------------------------------------------------------------------------
// Launch
// ---------------------------------------------------------------------------
extern "C" void kernel_launch(void* const* d_in, const int* in_sizes, int n_in,
                              void* d_out, int out_size)
{
    const int*   sizes = (const int*)  d_in[0];
    const float* feat  = (const float*)d_in[1];
    const float* We0   = (const float*)d_in[2];
    const float* be0   = (const float*)d_in[3];
    const float* We1   = (const float*)d_in[4];
    const float* be1   = (const float*)d_in[5];
    const float* Wih   = (const float*)d_in[6];
    const float* bih   = (const float*)d_in[7];
    const float* Whh   = (const float*)d_in[8];
    const float* bhh   = (const float*)d_in[9];
    const float* Wl0   = (const float*)d_in[10];
    const float* bl0   = (const float*)d_in[11];
    const float* Wl1   = (const float*)d_in[12];
    const float* bl1   = (const float*)d_in[13];
    const float* Wd    = (const float*)d_in[14];
    const float* bd    = (const float*)d_in[15];

    const int B  = in_sizes[0];
    const int K0 = in_sizes[2] / HID;     // IN_DIM (164)
    const int T  = in_sizes[1] / K0;

    float *x1, *x2, *xproj, *h0, *h1, *cst, *t0, *t1;
    int *starts;
    cudaGetSymbolAddress((void**)&x1,    g_x1);
    cudaGetSymbolAddress((void**)&x2,    g_x2);
    cudaGetSymbolAddress((void**)&xproj, g_xproj);
    cudaGetSymbolAddress((void**)&h0,    g_h0);
    cudaGetSymbolAddress((void**)&h1,    g_h1);
    cudaGetSymbolAddress((void**)&cst,   g_c);
    cudaGetSymbolAddress((void**)&t0,    g_t0);
    cudaGetSymbolAddress((void**)&t1,    g_t1);
    cudaGetSymbolAddress((void**)&starts, g_starts);

    scan_starts_kernel<<<1, BMAX>>>(sizes, starts, B);

    int nz = B * HID;
    fill_zero_kernel<<<(nz + 255) / 256, 256>>>(h0, nz);
    fill_zero_kernel<<<(nz + 255) / 256, 256>>>(cst, nz);

    int mblk = (T + BM - 1) / BM;
    // encoder layer 0: x1 = relu(feat @ We0^T + be0)
    gemm_nt_kernel<<<dim3(HID / BN, mblk), 256>>>(feat, We0, be0, nullptr, x1, T, HID, K0, 1);
    // encoder layer 1: x2 = relu(x1 @ We1^T + be1)
    gemm_nt_kernel<<<dim3(HID / BN, mblk), 256>>>(x1, We1, be1, nullptr, x2, T, HID, HID, 1);
    // x projection: xproj = x2 @ Wih^T   (bias added inside the step)
    gemm_nt_kernel<<<dim3(GATES / BN, mblk), 256>>>(x2, Wih, nullptr, nullptr, xproj, T, GATES, HID, 0);

    // LSTM: 128 fused steps, h ping-pong
    for (int t = 0; t < MAXLEN; t++) {
        const float* hp = (t & 1) ? h1 : h0;
        float*       hn = (t & 1) ? h0 : h1;
        lstm_step_kernel<<<dim3(HID / 16, B / BM), 256>>>(hp, hn, cst, Whh, bih, bhh,
                                                          xproj, starts, sizes, t, B);
    }
    const float* hf = h0;  // MAXLEN even -> final h in h0

    // residual MLPs
    gemm_nt_kernel<<<dim3(HID / BN, B / BM), 256>>>(hf, Wl0, bl0, hf, t0, B, HID, HID, 2);
    gemm_nt_kernel<<<dim3(HID / BN, B / BM), 256>>>(t0, Wl1, bl1, t0, t1, B, HID, HID, 2);

    // decoder
    decoder_kernel<<<(B * 32 + 255) / 256, 256>>>(t1, Wd, bd, (float*)d_out, B);
}

// round 4
// speedup vs baseline: 3.1881x; 3.1881x over previous
#include <cuda_runtime.h>
#include <cuda_fp16.h>
#include <cuda_bf16.h>
#include <math.h>
#include <stdint.h>

// ---------------------------------------------------------------------------
// Problem constants
// ---------------------------------------------------------------------------
#define HID    512
#define GATES  2048
#define MAXLEN 128
#define BMAX   1024
#define TMAX   (BMAX * 127)
#define K0PAD  192           // 164 padded to multiple of 32

// ---------------------------------------------------------------------------
// Scratch
// ---------------------------------------------------------------------------
__device__ __half g_feat16[(size_t)TMAX * K0PAD];
__device__ __half g_x1h  [(size_t)TMAX * HID];
__device__ __half g_x2h  [(size_t)TMAX * HID];
__device__ __half g_xp16 [(size_t)TMAX * GATES];
__device__ __half g_We0h [HID * K0PAD];
__device__ __half g_We1h [HID * HID];
__device__ __half g_Wihh [GATES * HID];
__device__ __half g_Whh2 [(size_t)GATES * 1024];   // [2048][1024]: hi | lo
__device__ __half g_h2   [BMAX * 1024];            // duplicated h
__device__ float  g_gates[(size_t)BMAX * GATES];
__device__ float  g_c    [BMAX * HID];
__device__ float  g_hf   [BMAX * HID];
__device__ float  g_t0   [BMAX * HID];
__device__ float  g_t1   [BMAX * HID];
__device__ int    g_starts[BMAX];

// ---------------------------------------------------------------------------
// Small helpers
// ---------------------------------------------------------------------------
__device__ __forceinline__ uint32_t smem_u32(const void* p) {
    return (uint32_t)__cvta_generic_to_shared(p);
}
__device__ __forceinline__ void cp_async16(void* dst, const void* src, bool pred) {
    uint32_t d = smem_u32(dst);
    int sz = pred ? 16 : 0;
    asm volatile("cp.async.cg.shared.global [%0], [%1], 16, %2;\n"
                 :: "r"(d), "l"(src), "r"(sz));
}
__device__ __forceinline__ void cp_commit() { asm volatile("cp.async.commit_group;\n"); }
template<int N> __device__ __forceinline__ void cp_wait() {
    asm volatile("cp.async.wait_group %0;\n" :: "n"(N));
}
__device__ __forceinline__ void ldm_x4(uint32_t addr, uint32_t& r0, uint32_t& r1,
                                       uint32_t& r2, uint32_t& r3) {
    asm volatile("ldmatrix.sync.aligned.m8n8.x4.shared.b16 {%0,%1,%2,%3}, [%4];"
                 : "=r"(r0), "=r"(r1), "=r"(r2), "=r"(r3) : "r"(addr));
}
__device__ __forceinline__ void mma16816(float* c, const uint32_t* a, const uint32_t* b) {
    asm volatile("mma.sync.aligned.m16n8k16.row.col.f32.f16.f16.f32 "
                 "{%0,%1,%2,%3}, {%4,%5,%6,%7}, {%8,%9}, {%0,%1,%2,%3};"
                 : "+f"(c[0]), "+f"(c[1]), "+f"(c[2]), "+f"(c[3])
                 : "r"(a[0]), "r"(a[1]), "r"(a[2]), "r"(a[3]), "r"(b[0]), "r"(b[1]));
}

// ---------------------------------------------------------------------------
// setup kernels
// ---------------------------------------------------------------------------
__global__ void scan_starts_kernel(const int* __restrict__ sizes, int* __restrict__ starts, int B) {
    __shared__ int s[BMAX];
    int tid = threadIdx.x;
    if (tid < B) s[tid] = sizes[tid];
    __syncthreads();
    if (tid == 0) {
        int acc = 0;
        for (int i = 0; i < B; i++) { starts[i] = acc; acc += s[i]; }
    }
}
__global__ void fill_zero_f(float* __restrict__ p, int n) {
    int i = blockIdx.x * blockDim.x + threadIdx.x;
    if (i < n) p[i] = 0.f;
}
__global__ void fill_zero_h(__half* __restrict__ p, int n) {
    int i = blockIdx.x * blockDim.x + threadIdx.x;
    if (i < n) p[i] = __float2half(0.f);
}
// fp32 -> fp16 with column padding (Cp >= C, pad zero)
__global__ void f2h_pad(const float* __restrict__ src, __half* __restrict__ dst,
                        int R, int C, int Cp) {
    int i = blockIdx.x * blockDim.x + threadIdx.x;
    if (i >= R * Cp) return;
    int r = i / Cp, c = i - r * Cp;
    dst[i] = __float2half(c < C ? src[(size_t)r * C + c] : 0.f);
}
// Whh [2048][512] fp32 -> [2048][1024] fp16 (hi | lo split)
__global__ void whh_split(const float* __restrict__ w, __half* __restrict__ dst) {
    int i = blockIdx.x * blockDim.x + threadIdx.x;
    if (i >= GATES * HID) return;
    int r = i >> 9, c = i & 511;
    float v = w[i];
    __half hi = __float2half(v);
    __half lo = __float2half(v - __half2float(hi));
    dst[(size_t)r * 1024 + c] = hi;
    dst[(size_t)r * 1024 + 512 + c] = lo;
}

// ---------------------------------------------------------------------------
// fp16 NT GEMM with fp32 accumulate:
//   C[M,N] = act(A[M,K] @ B[N,K]^T + bias)
// BM=128 BN=128 BK=32, 256 threads, warp tile 32x64, mma m16n8k16.
// K must be a multiple of 32; N a multiple of 128.
// ---------------------------------------------------------------------------
template<bool OUT_HALF, bool RELU, bool HAS_BIAS>
__global__ __launch_bounds__(256, 1)
void hgemm_nt(const __half* __restrict__ A, const __half* __restrict__ B,
              const float* __restrict__ bias, void* __restrict__ Cout,
              int M, int N, int K)
{
    __shared__ __half As[2][128][40];
    __shared__ __half Bs[2][128][40];

    const int m0 = blockIdx.y * 128;
    const int n0 = blockIdx.x * 128;
    const int tid = threadIdx.x;
    const int warp = tid >> 5, lane = tid & 31;
    const int wm = (warp & 3) * 32;
    const int wn = (warp >> 2) * 64;

    float acc[2][8][4];
    #pragma unroll
    for (int i = 0; i < 2; i++)
        #pragma unroll
        for (int j = 0; j < 8; j++)
            #pragma unroll
            for (int q = 0; q < 4; q++) acc[i][j][q] = 0.f;

    const int KT = K >> 5;
    const int lrow = tid >> 1;

    // prologue load (buf 0, kt 0)
    {
        #pragma unroll
        for (int i = 0; i < 2; i++) {
            int ch = (tid & 1) * 2 + i;
            int col = ch * 8;
            int gm = m0 + lrow;
            bool p = gm < M;
            const __half* gs = A + (size_t)(p ? gm : 0) * K + col;
            cp_async16(&As[0][lrow][col], gs, p);
        }
        #pragma unroll
        for (int i = 0; i < 2; i++) {
            int ch = (tid & 1) * 2 + i;
            int col = ch * 8;
            int gn = n0 + lrow;
            const __half* gs = B + (size_t)gn * K + col;
            cp_async16(&Bs[0][lrow][col], gs, true);
        }
        cp_commit();
    }

    for (int kt = 0; kt < KT; kt++) {
        const int buf = kt & 1;
        if (kt + 1 < KT) {
            const int k0 = (kt + 1) << 5;
            #pragma unroll
            for (int i = 0; i < 2; i++) {
                int ch = (tid & 1) * 2 + i;
                int col = ch * 8;
                int gm = m0 + lrow;
                bool p = gm < M;
                const __half* gs = A + (size_t)(p ? gm : 0) * K + k0 + col;
                cp_async16(&As[buf ^ 1][lrow][col], gs, p);
            }
            #pragma unroll
            for (int i = 0; i < 2; i++) {
                int ch = (tid & 1) * 2 + i;
                int col = ch * 8;
                int gn = n0 + lrow;
                const __half* gs = B + (size_t)gn * K + k0 + col;
                cp_async16(&Bs[buf ^ 1][lrow][col], gs, true);
            }
            cp_commit();
            cp_wait<1>();
        } else {
            cp_wait<0>();
        }
        __syncthreads();

        #pragma unroll
        for (int s = 0; s < 2; s++) {
            uint32_t afrag[2][4];
            #pragma unroll
            for (int mi = 0; mi < 2; mi++) {
                int r = wm + mi * 16 + (lane & 15);
                int c = s * 16 + (lane >> 4) * 8;
                ldm_x4(smem_u32(&As[buf][r][c]),
                       afrag[mi][0], afrag[mi][1], afrag[mi][2], afrag[mi][3]);
            }
            uint32_t bfrag[8][2];
            #pragma unroll
            for (int njp = 0; njp < 4; njp++) {
                int g = lane >> 3;
                int nrow = wn + njp * 16 + (g >> 1) * 8 + (lane & 7);
                int c = s * 16 + (g & 1) * 8;
                uint32_t r0, r1, r2, r3;
                ldm_x4(smem_u32(&Bs[buf][nrow][c]), r0, r1, r2, r3);
                bfrag[njp * 2][0] = r0; bfrag[njp * 2][1] = r1;
                bfrag[njp * 2 + 1][0] = r2; bfrag[njp * 2 + 1][1] = r3;
            }
            #pragma unroll
            for (int mi = 0; mi < 2; mi++)
                #pragma unroll
                for (int ni = 0; ni < 8; ni++)
                    mma16816(acc[mi][ni], afrag[mi], bfrag[ni]);
        }
        __syncthreads();
    }

    // epilogue
    const int r_lo = lane >> 2;
    const int cpair = (lane & 3) * 2;
    #pragma unroll
    for (int mi = 0; mi < 2; mi++) {
        #pragma unroll
        for (int half_row = 0; half_row < 2; half_row++) {
            int gr = m0 + wm + mi * 16 + r_lo + half_row * 8;
            if (gr >= M) continue;
            #pragma unroll
            for (int ni = 0; ni < 8; ni++) {
                int gc = n0 + wn + ni * 8 + cpair;
                float v0 = acc[mi][ni][half_row * 2 + 0];
                float v1 = acc[mi][ni][half_row * 2 + 1];
                if (HAS_BIAS) { v0 += bias[gc]; v1 += bias[gc + 1]; }
                if (RELU) { v0 = fmaxf(v0, 0.f); v1 = fmaxf(v1, 0.f); }
                if (OUT_HALF) {
                    __half2 hv;
                    hv.x = __float2half(v0); hv.y = __float2half(v1);
                    *reinterpret_cast<__half2*>((__half*)Cout + (size_t)gr * N + gc) = hv;
                } else {
                    float2 fv = make_float2(v0, v1);
                    *reinterpret_cast<float2*>((float*)Cout + (size_t)gr * N + gc) = fv;
                }
            }
        }
    }
}

// ---------------------------------------------------------------------------
// LSTM elementwise update: gates (fp32) + bias + ragged xproj gather -> c,h
// ---------------------------------------------------------------------------
__global__ void lstm_update_kernel(
    const float* __restrict__ gates, const __half* __restrict__ xp16,
    float* __restrict__ c, __half* __restrict__ h2, float* __restrict__ hf,
    const float* __restrict__ bih, const float* __restrict__ bhh,
    const int* __restrict__ starts, const int* __restrict__ sizes,
    int t, int B, int write_hf)
{
    int idx = blockIdx.x * blockDim.x + threadIdx.x;
    if (idx >= B * HID) return;
    int b = idx >> 9, hid = idx & 511;
    size_t gb = (size_t)b * GATES;
    float gi = gates[gb + 0 * HID + hid] + bih[0 * HID + hid] + bhh[0 * HID + hid];
    float gf = gates[gb + 1 * HID + hid] + bih[1 * HID + hid] + bhh[1 * HID + hid];
    float gg = gates[gb + 2 * HID + hid] + bih[2 * HID + hid] + bhh[2 * HID + hid];
    float go = gates[gb + 3 * HID + hid] + bih[3 * HID + hid] + bhh[3 * HID + hid];
    if (t < sizes[b]) {
        size_t base = (size_t)(starts[b] + t) * GATES;
        gi += __half2float(xp16[base + 0 * HID + hid]);
        gf += __half2float(xp16[base + 1 * HID + hid]);
        gg += __half2float(xp16[base + 2 * HID + hid]);
        go += __half2float(xp16[base + 3 * HID + hid]);
    }
    float is = 1.f / (1.f + __expf(-gi));
    float fs = 1.f / (1.f + __expf(-gf));
    float gt = tanhf(gg);
    float os = 1.f / (1.f + __expf(-go));
    float cn = fs * c[idx] + is * gt;
    c[idx] = cn;
    float hn = os * tanhf(cn);
    __half hh = __float2half(hn);
    h2[(size_t)b * 1024 + hid] = hh;
    h2[(size_t)b * 1024 + 512 + hid] = hh;
    if (write_hf) hf[idx] = hn;
}

// ---------------------------------------------------------------------------
// fp32 tail GEMM (small: B=1024 rows): C = relu(A@B^T + bias) + R
// ---------------------------------------------------------------------------
#define BM 64
#define BN 64
#define BK 16
__global__ __launch_bounds__(256) void gemm_nt_kernel(
    const float* __restrict__ A, const float* __restrict__ B,
    const float* __restrict__ bias, const float* __restrict__ R,
    float* __restrict__ C, int M, int N, int K)
{
    __shared__ float As[BK][BM];
    __shared__ float Bs[BK][BN];
    const int m0 = blockIdx.y * BM;
    const int n0 = blockIdx.x * BN;
    const int tid = threadIdx.x;
    const int tx = tid & 15, ty = tid >> 4;
    const int lrow = tid >> 2, lkq = (tid & 3) * 4;
    float acc[4][4] = {};
    for (int k0 = 0; k0 < K; k0 += BK) {
        {
            int gm = m0 + lrow;
            float4 v = make_float4(0.f, 0.f, 0.f, 0.f);
            if (gm < M) v = *reinterpret_cast<const float4*>(A + (size_t)gm * K + k0 + lkq);
            As[lkq + 0][lrow] = v.x; As[lkq + 1][lrow] = v.y;
            As[lkq + 2][lrow] = v.z; As[lkq + 3][lrow] = v.w;
        }
        {
            float4 v = *reinterpret_cast<const float4*>(B + (size_t)(n0 + lrow) * K + k0 + lkq);
            Bs[lkq + 0][lrow] = v.x; Bs[lkq + 1][lrow] = v.y;
            Bs[lkq + 2][lrow] = v.z; Bs[lkq + 3][lrow] = v.w;
        }
        __syncthreads();
        #pragma unroll
        for (int k = 0; k < BK; k++) {
            float4 a = *reinterpret_cast<const float4*>(&As[k][ty * 4]);
            float4 b = *reinterpret_cast<const float4*>(&Bs[k][tx * 4]);
            acc[0][0] += a.x * b.x; acc[0][1] += a.x * b.y; acc[0][2] += a.x * b.z; acc[0][3] += a.x * b.w;
            acc[1][0] += a.y * b.x; acc[1][1] += a.y * b.y; acc[1][2] += a.y * b.z; acc[1][3] += a.y * b.w;
            acc[2][0] += a.z * b.x; acc[2][1] += a.z * b.y; acc[2][2] += a.z * b.z; acc[2][3] += a.z * b.w;
            acc[3][0] += a.w * b.x; acc[3][1] += a.w * b.y; acc[3][2] += a.w * b.z; acc[3][3] += a.w * b.w;
        }
        __syncthreads();
    }
    #pragma unroll
    for (int i = 0; i < 4; i++) {
        int gm = m0 + ty * 4 + i;
        if (gm >= M) continue;
        #pragma unroll
        for (int j = 0; j < 4; j++) {
            int gn = n0 + tx * 4 + j;
            float v = acc[i][j] + bias[gn];
            v = fmaxf(v, 0.f);
            v += R[(size_t)gm * N + gn];
            C[(size_t)gm * N + gn] = v;
        }
    }
}

__global__ void decoder_kernel(const float* __restrict__ X, const float* __restrict__ Wd,
                               const float* __restrict__ bd, float* __restrict__ out, int B)
{
    int warp = (blockIdx.x * blockDim.x + threadIdx.x) >> 5;
    int lane = threadIdx.x & 31;
    if (warp >= B) return;
    const float4* row = reinterpret_cast<const float4*>(X + (size_t)warp * HID);
    const float4* w = reinterpret_cast<const float4*>(Wd);
    float s = 0.f;
    #pragma unroll
    for (int i = lane; i < HID / 4; i += 32) {
        float4 a = row[i], bw = w[i];
        s += a.x * bw.x + a.y * bw.y + a.z * bw.z + a.w * bw.w;
    }
    #pragma unroll
    for (int o = 16; o > 0; o >>= 1) s += __shfl_down_sync(0xffffffffu, s, o);
    if (lane == 0) out[warp] = s + bd[0];
}

// ---------------------------------------------------------------------------
// Launch
// ---------------------------------------------------------------------------
extern "C" void kernel_launch(void* const* d_in, const int* in_sizes, int n_in,
                              void* d_out, int out_size)
{
    const int*   sizes = (const int*)  d_in[0];
    const float* feat  = (const float*)d_in[1];
    const float* We0   = (const float*)d_in[2];
    const float* be0   = (const float*)d_in[3];
    const float* We1   = (const float*)d_in[4];
    const float* be1   = (const float*)d_in[5];
    const float* Wih   = (const float*)d_in[6];
    const float* bih   = (const float*)d_in[7];
    const float* Whh   = (const float*)d_in[8];
    const float* bhh   = (const float*)d_in[9];
    const float* Wl0   = (const float*)d_in[10];
    const float* bl0   = (const float*)d_in[11];
    const float* Wl1   = (const float*)d_in[12];
    const float* bl1   = (const float*)d_in[13];
    const float* Wd    = (const float*)d_in[14];
    const float* bd    = (const float*)d_in[15];

    const int B  = in_sizes[0];
    const int K0 = in_sizes[2] / HID;        // 164
    const int T  = in_sizes[1] / K0;

    __half *feat16, *x1h, *x2h, *xp16, *We0h, *We1h, *Wihh, *Whh2, *h2;
    float *gates, *cst, *hf, *t0, *t1;
    int *starts;
    cudaGetSymbolAddress((void**)&feat16, g_feat16);
    cudaGetSymbolAddress((void**)&x1h,   g_x1h);
    cudaGetSymbolAddress((void**)&x2h,   g_x2h);
    cudaGetSymbolAddress((void**)&xp16,  g_xp16);
    cudaGetSymbolAddress((void**)&We0h,  g_We0h);
    cudaGetSymbolAddress((void**)&We1h,  g_We1h);
    cudaGetSymbolAddress((void**)&Wihh,  g_Wihh);
    cudaGetSymbolAddress((void**)&Whh2,  g_Whh2);
    cudaGetSymbolAddress((void**)&h2,    g_h2);
    cudaGetSymbolAddress((void**)&gates, g_gates);
    cudaGetSymbolAddress((void**)&cst,   g_c);
    cudaGetSymbolAddress((void**)&hf,    g_hf);
    cudaGetSymbolAddress((void**)&t0,    g_t0);
    cudaGetSymbolAddress((void**)&t1,    g_t1);
    cudaGetSymbolAddress((void**)&starts, g_starts);

    scan_starts_kernel<<<1, BMAX>>>(sizes, starts, B);

    // conversions
    {
        int n = T * K0PAD;
        f2h_pad<<<(n + 255) / 256, 256>>>(feat, feat16, T, K0, K0PAD);
        n = HID * K0PAD;
        f2h_pad<<<(n + 255) / 256, 256>>>(We0, We0h, HID, K0, K0PAD);
        n = HID * HID;
        f2h_pad<<<(n + 255) / 256, 256>>>(We1, We1h, HID, HID, HID);
        n = GATES * HID;
        f2h_pad<<<(n + 255) / 256, 256>>>(Wih, Wihh, GATES, HID, HID);
        whh_split<<<(GATES * HID + 255) / 256, 256>>>(Whh, Whh2);
    }
    // zero states
    fill_zero_f<<<(B * HID + 255) / 256, 256>>>(cst, B * HID);
    fill_zero_h<<<(B * 1024 + 255) / 256, 256>>>(h2, B * 1024);

    const int mblkT = (T + 127) / 128;
    // encoder L0: x1 = relu(feat16 @ We0h^T + be0)   [T,512] K=192
    hgemm_nt<true, true, true><<<dim3(HID / 128, mblkT), 256>>>(
        feat16, We0h, be0, x1h, T, HID, K0PAD);
    // encoder L1: x2 = relu(x1 @ We1h^T + be1)       [T,512] K=512
    hgemm_nt<true, true, true><<<dim3(HID / 128, mblkT), 256>>>(
        x1h, We1h, be1, x2h, T, HID, HID);
    // xproj = x2 @ Wih^T                              [T,2048] K=512
    hgemm_nt<true, false, false><<<dim3(GATES / 128, mblkT), 256>>>(
        x2h, Wihh, nullptr, xp16, T, GATES, HID);

    // LSTM steps
    const int mblkB = (B + 127) / 128;
    for (int t = 0; t < MAXLEN; t++) {
        hgemm_nt<false, false, false><<<dim3(GATES / 128, mblkB), 256>>>(
            h2, Whh2, nullptr, gates, B, GATES, 1024);
        lstm_update_kernel<<<(B * HID + 255) / 256, 256>>>(
            gates, xp16, cst, h2, hf, bih, bhh, starts, sizes,
            t, B, (t == MAXLEN - 1) ? 1 : 0);
    }

    // tail (fp32)
    gemm_nt_kernel<<<dim3(HID / BN, B / BM), 256>>>(hf, Wl0, bl0, hf, t0, B, HID, HID);
    gemm_nt_kernel<<<dim3(HID / BN, B / BM), 256>>>(t0, Wl1, bl1, t0, t1, B, HID, HID);
    decoder_kernel<<<(B * 32 + 255) / 256, 256>>>(t1, Wd, bd, (float*)d_out, B);
}

// round 5
// speedup vs baseline: 3.7441x; 1.1744x over previous
#include <cuda_runtime.h>
#include <cuda_fp16.h>
#include <math.h>
#include <stdint.h>

// ---------------------------------------------------------------------------
// Problem constants
// ---------------------------------------------------------------------------
#define HID    512
#define GATES  2048
#define MAXLEN 128
#define BMAX   1024
#define TMAX   (BMAX * 127)
#define K0PAD  192
#define NCTA   128         // persistent LSTM grid (16 nblk x 8 mblk)

// ---------------------------------------------------------------------------
// Scratch
// ---------------------------------------------------------------------------
__device__ __half g_feat16[(size_t)TMAX * K0PAD];
__device__ __half g_x1h  [(size_t)TMAX * HID];
__device__ __half g_x2h  [(size_t)TMAX * HID];
__device__ __half g_xp16 [(size_t)TMAX * GATES];
__device__ __half g_We0h [HID * K0PAD];
__device__ __half g_We1h [HID * HID];
__device__ __half g_Wihp [GATES * HID];     // gate-interleaved rows
__device__ __half g_Whhp [GATES * HID];     // gate-interleaved rows
__device__ float  g_bsum [GATES];           // gate-interleaved bih+bhh
__device__ __half g_h0   [BMAX * HID];
__device__ __half g_h1   [BMAX * HID];
__device__ float  g_hf   [BMAX * HID];
__device__ float  g_t0   [BMAX * HID];
__device__ float  g_t1   [BMAX * HID];
__device__ int    g_starts[BMAX];
__device__ unsigned          g_cnt = 0;
__device__ volatile unsigned g_gen = 0;

// ---------------------------------------------------------------------------
// Helpers
// ---------------------------------------------------------------------------
__device__ __forceinline__ uint32_t smem_u32(const void* p) {
    return (uint32_t)__cvta_generic_to_shared(p);
}
__device__ __forceinline__ void cp_async16(void* dst, const void* src, bool pred) {
    uint32_t d = smem_u32(dst);
    int sz = pred ? 16 : 0;
    asm volatile("cp.async.cg.shared.global [%0], [%1], 16, %2;\n"
                 :: "r"(d), "l"(src), "r"(sz));
}
__device__ __forceinline__ void cp_commit() { asm volatile("cp.async.commit_group;\n"); }
template<int N> __device__ __forceinline__ void cp_wait() {
    asm volatile("cp.async.wait_group %0;\n" :: "n"(N));
}
__device__ __forceinline__ void ldm_x4(uint32_t addr, uint32_t& r0, uint32_t& r1,
                                       uint32_t& r2, uint32_t& r3) {
    asm volatile("ldmatrix.sync.aligned.m8n8.x4.shared.b16 {%0,%1,%2,%3}, [%4];"
                 : "=r"(r0), "=r"(r1), "=r"(r2), "=r"(r3) : "r"(addr));
}
__device__ __forceinline__ void mma16816(float* c, const uint32_t* a, const uint32_t* b) {
    asm volatile("mma.sync.aligned.m16n8k16.row.col.f32.f16.f16.f32 "
                 "{%0,%1,%2,%3}, {%4,%5,%6,%7}, {%8,%9}, {%0,%1,%2,%3};"
                 : "+f"(c[0]), "+f"(c[1]), "+f"(c[2]), "+f"(c[3])
                 : "r"(a[0]), "r"(a[1]), "r"(a[2]), "r"(a[3]), "r"(b[0]), "r"(b[1]));
}

// ---------------------------------------------------------------------------
// setup kernels
// ---------------------------------------------------------------------------
__global__ void scan_starts_kernel(const int* __restrict__ sizes, int* __restrict__ starts, int B) {
    __shared__ int s[BMAX];
    int tid = threadIdx.x;
    if (tid < B) s[tid] = sizes[tid];
    __syncthreads();
    if (tid == 0) {
        int acc = 0;
        for (int i = 0; i < B; i++) { starts[i] = acc; acc += s[i]; }
    }
}
__global__ void fill_zero_h(__half* __restrict__ p, int n) {
    int i = blockIdx.x * blockDim.x + threadIdx.x;
    if (i < n) p[i] = __float2half(0.f);
}
__global__ void f2h_pad(const float* __restrict__ src, __half* __restrict__ dst,
                        int R, int C, int Cp) {
    int i = blockIdx.x * blockDim.x + threadIdx.x;
    if (i >= R * Cp) return;
    int r = i / Cp, c = i - r * Cp;
    dst[i] = __float2half(c < C ? src[(size_t)r * C + c] : 0.f);
}
// permute rows g*512+hid -> hid*4+g, fp32->fp16  (W is [2048][512])
__global__ void perm_rows_h(const float* __restrict__ w, __half* __restrict__ dst) {
    int i = blockIdx.x * blockDim.x + threadIdx.x;
    if (i >= GATES * HID) return;
    int r = i >> 9, c = i & 511;
    int g = r >> 9, hid = r & 511;
    dst[(size_t)(hid * 4 + g) * HID + c] = __float2half(w[i]);
}
__global__ void bsum_kernel(const float* __restrict__ bih, const float* __restrict__ bhh,
                            float* __restrict__ bsum) {
    int o = blockIdx.x * blockDim.x + threadIdx.x;
    if (o >= GATES) return;
    int hid = o >> 2, g = o & 3;
    bsum[o] = bih[g * HID + hid] + bhh[g * HID + hid];
}
__global__ void h2f_kernel(const __half* __restrict__ src, float* __restrict__ dst, int n) {
    int i = blockIdx.x * blockDim.x + threadIdx.x;
    if (i < n) dst[i] = __half2float(src[i]);
}

// ---------------------------------------------------------------------------
// fp16 NT GEMM (encoder / xproj), same as round 4
// ---------------------------------------------------------------------------
template<bool RELU, bool HAS_BIAS>
__global__ __launch_bounds__(256, 1)
void hgemm_nt(const __half* __restrict__ A, const __half* __restrict__ B,
              const float* __restrict__ bias, __half* __restrict__ Cout,
              int M, int N, int K)
{
    __shared__ __half As[2][128][40];
    __shared__ __half Bs[2][128][40];

    const int m0 = blockIdx.y * 128;
    const int n0 = blockIdx.x * 128;
    const int tid = threadIdx.x;
    const int warp = tid >> 5, lane = tid & 31;
    const int wm = (warp & 3) * 32;
    const int wn = (warp >> 2) * 64;

    float acc[2][8][4];
    #pragma unroll
    for (int i = 0; i < 2; i++)
        #pragma unroll
        for (int j = 0; j < 8; j++)
            #pragma unroll
            for (int q = 0; q < 4; q++) acc[i][j][q] = 0.f;

    const int KT = K >> 5;
    const int lrow = tid >> 1;

    {
        #pragma unroll
        for (int i = 0; i < 2; i++) {
            int col = ((tid & 1) * 2 + i) * 8;
            int gm = m0 + lrow;
            bool p = gm < M;
            cp_async16(&As[0][lrow][col], A + (size_t)(p ? gm : 0) * K + col, p);
        }
        #pragma unroll
        for (int i = 0; i < 2; i++) {
            int col = ((tid & 1) * 2 + i) * 8;
            cp_async16(&Bs[0][lrow][col], B + (size_t)(n0 + lrow) * K + col, true);
        }
        cp_commit();
    }

    for (int kt = 0; kt < KT; kt++) {
        const int buf = kt & 1;
        if (kt + 1 < KT) {
            const int k0 = (kt + 1) << 5;
            #pragma unroll
            for (int i = 0; i < 2; i++) {
                int col = ((tid & 1) * 2 + i) * 8;
                int gm = m0 + lrow;
                bool p = gm < M;
                cp_async16(&As[buf ^ 1][lrow][col], A + (size_t)(p ? gm : 0) * K + k0 + col, p);
            }
            #pragma unroll
            for (int i = 0; i < 2; i++) {
                int col = ((tid & 1) * 2 + i) * 8;
                cp_async16(&Bs[buf ^ 1][lrow][col], B + (size_t)(n0 + lrow) * K + k0 + col, true);
            }
            cp_commit();
            cp_wait<1>();
        } else {
            cp_wait<0>();
        }
        __syncthreads();

        #pragma unroll
        for (int s = 0; s < 2; s++) {
            uint32_t afrag[2][4];
            #pragma unroll
            for (int mi = 0; mi < 2; mi++) {
                int r = wm + mi * 16 + (lane & 15);
                int c = s * 16 + (lane >> 4) * 8;
                ldm_x4(smem_u32(&As[buf][r][c]),
                       afrag[mi][0], afrag[mi][1], afrag[mi][2], afrag[mi][3]);
            }
            uint32_t bfrag[8][2];
            #pragma unroll
            for (int njp = 0; njp < 4; njp++) {
                int g = lane >> 3;
                int nrow = wn + njp * 16 + (g >> 1) * 8 + (lane & 7);
                int c = s * 16 + (g & 1) * 8;
                uint32_t r0, r1, r2, r3;
                ldm_x4(smem_u32(&Bs[buf][nrow][c]), r0, r1, r2, r3);
                bfrag[njp * 2][0] = r0; bfrag[njp * 2][1] = r1;
                bfrag[njp * 2 + 1][0] = r2; bfrag[njp * 2 + 1][1] = r3;
            }
            #pragma unroll
            for (int mi = 0; mi < 2; mi++)
                #pragma unroll
                for (int ni = 0; ni < 8; ni++)
                    mma16816(acc[mi][ni], afrag[mi], bfrag[ni]);
        }
        __syncthreads();
    }

    const int r_lo = lane >> 2;
    const int cpair = (lane & 3) * 2;
    #pragma unroll
    for (int mi = 0; mi < 2; mi++) {
        #pragma unroll
        for (int hr = 0; hr < 2; hr++) {
            int gr = m0 + wm + mi * 16 + r_lo + hr * 8;
            if (gr >= M) continue;
            #pragma unroll
            for (int ni = 0; ni < 8; ni++) {
                int gc = n0 + wn + ni * 8 + cpair;
                float v0 = acc[mi][ni][hr * 2 + 0];
                float v1 = acc[mi][ni][hr * 2 + 1];
                if (HAS_BIAS) { v0 += bias[gc]; v1 += bias[gc + 1]; }
                if (RELU) { v0 = fmaxf(v0, 0.f); v1 = fmaxf(v1, 0.f); }
                __half2 hv;
                hv.x = __float2half(v0); hv.y = __float2half(v1);
                *reinterpret_cast<__half2*>(Cout + (size_t)gr * N + gc) = hv;
            }
        }
    }
}

// ---------------------------------------------------------------------------
// Persistent LSTM kernel: all 128 steps, Whh resident in smem, c in registers,
// fused epilogue (bias + ragged xproj + sigmoid/tanh + c/h update).
// Grid = 128 CTAs (16 nblk x 8 mblk), 256 threads, 1 CTA/SM.
// ---------------------------------------------------------------------------
// dyn smem layout (bytes):
//   WhS    [128][520] half : 0      .. 133120
//   AS [2] [128][40]  half : 133120 .. 153600
//   bsS    [128] float     : 153600 .. 154112
//   stS    [128] int       : 154112 .. 154624
//   szS    [128] int       : 154624 .. 155136
//   hS     [128][32] half  : 155136 .. 163328
#define LSTM_SMEM 163328

__device__ __forceinline__ void grid_sync_128() {
    __syncthreads();
    if (threadIdx.x == 0) {
        __threadfence();
        unsigned gen = g_gen;
        if (atomicAdd(&g_cnt, 1) == NCTA - 1) {
            g_cnt = 0;
            __threadfence();
            g_gen = gen + 1;
        } else {
            while (g_gen == gen) { __nanosleep(32); }
        }
    }
    __syncthreads();
}

__global__ __launch_bounds__(256, 1)
void lstm_persist(const __half* __restrict__ Whp, const __half* __restrict__ xp,
                  const float* __restrict__ bsum,
                  const int* __restrict__ starts, const int* __restrict__ sizes,
                  __half* __restrict__ hbuf0, __half* __restrict__ hbuf1)
{
    extern __shared__ char smem[];
    __half* WhS = (__half*)(smem);
    __half* AS  = (__half*)(smem + 133120);   // [2][128][40]
    float*  bsS = (float*) (smem + 153600);
    int*    stS = (int*)   (smem + 154112);
    int*    szS = (int*)   (smem + 154624);
    __half* hS  = (__half*)(smem + 155136);   // [128][32]

    const int tid  = threadIdx.x;
    const int warp = tid >> 5, lane = tid & 31;
    const int nblk = blockIdx.x & 15, mblk = blockIdx.x >> 4;
    const int n0 = nblk * 128, m0 = mblk * 128;
    const int wm = (warp & 3) * 32, wn = (warp >> 2) * 64;
    const int lrow = tid >> 1;

    // ---- load resident Whh slice (gate-interleaved rows n0..n0+127) ----
    for (int i = tid; i < 128 * 64; i += 256) {
        int r = i >> 6, ch = i & 63;
        cp_async16(&WhS[r * 520 + ch * 8], Whp + (size_t)(n0 + r) * HID + ch * 8, true);
    }
    cp_commit();
    for (int i = tid; i < 128; i += 256) {
        bsS[i] = bsum[n0 + i];
        stS[i] = starts[m0 + i];
        szS[i] = sizes[m0 + i];
    }
    cp_wait<0>();
    __syncthreads();

    // c state in registers (even lanes hold the real values)
    float creg[2][2][8];
    #pragma unroll
    for (int mi = 0; mi < 2; mi++)
        #pragma unroll
        for (int hr = 0; hr < 2; hr++)
            #pragma unroll
            for (int ni = 0; ni < 8; ni++) creg[mi][hr][ni] = 0.f;

    for (int t = 0; t < MAXLEN; t++) {
        const __half* hA = (t & 1) ? hbuf1 : hbuf0;
        __half*       hN = (t & 1) ? hbuf0 : hbuf1;

        // prologue: A tile 0
        #pragma unroll
        for (int i = 0; i < 2; i++) {
            int col = ((tid & 1) * 2 + i) * 8;
            cp_async16(&AS[lrow * 40 + col], hA + (size_t)(m0 + lrow) * HID + col, true);
        }
        cp_commit();

        float acc[2][8][4];
        #pragma unroll
        for (int mi = 0; mi < 2; mi++)
            #pragma unroll
            for (int ni = 0; ni < 8; ni++)
                #pragma unroll
                for (int q = 0; q < 4; q++) acc[mi][ni][q] = 0.f;

        for (int kt = 0; kt < 16; kt++) {
            const int buf = kt & 1;
            if (kt < 15) {
                const int k0 = (kt + 1) << 5;
                #pragma unroll
                for (int i = 0; i < 2; i++) {
                    int col = ((tid & 1) * 2 + i) * 8;
                    cp_async16(&AS[(buf ^ 1) * 5120 + lrow * 40 + col],
                               hA + (size_t)(m0 + lrow) * HID + k0 + col, true);
                }
                cp_commit();
                cp_wait<1>();
            } else {
                cp_wait<0>();
            }
            __syncthreads();

            #pragma unroll
            for (int s = 0; s < 2; s++) {
                const int ks = kt * 2 + s;
                uint32_t afrag[2][4];
                #pragma unroll
                for (int mi = 0; mi < 2; mi++) {
                    int r = wm + mi * 16 + (lane & 15);
                    int c = s * 16 + (lane >> 4) * 8;
                    ldm_x4(smem_u32(&AS[buf * 5120 + r * 40 + c]),
                           afrag[mi][0], afrag[mi][1], afrag[mi][2], afrag[mi][3]);
                }
                uint32_t bfrag[8][2];
                #pragma unroll
                for (int njp = 0; njp < 4; njp++) {
                    int g = lane >> 3;
                    int nrow = wn + njp * 16 + (g >> 1) * 8 + (lane & 7);
                    int c = ks * 16 + (g & 1) * 8;
                    uint32_t r0, r1, r2, r3;
                    ldm_x4(smem_u32(&WhS[nrow * 520 + c]), r0, r1, r2, r3);
                    bfrag[njp * 2][0] = r0; bfrag[njp * 2][1] = r1;
                    bfrag[njp * 2 + 1][0] = r2; bfrag[njp * 2 + 1][1] = r3;
                }
                #pragma unroll
                for (int mi = 0; mi < 2; mi++)
                    #pragma unroll
                    for (int ni = 0; ni < 8; ni++)
                        mma16816(acc[mi][ni], afrag[mi], bfrag[ni]);
            }
            __syncthreads();
        }

        // ---- fused LSTM epilogue ----
        // cell for this lane pair: hid_local = (wn+ni*8)/4 + ((lane&3)>>1)
        // even lane holds (i,f), odd holds (g,o); shfl_xor(1) completes the set.
        const int hlq = (lane & 3) >> 1;
        const int rbase = wm + (lane >> 2);
        #pragma unroll
        for (int mi = 0; mi < 2; mi++) {
            #pragma unroll
            for (int hr = 0; hr < 2; hr++) {
                const int rl = rbase + mi * 16 + hr * 8;   // local batch row
                #pragma unroll
                for (int ni = 0; ni < 8; ni++) {
                    float v0 = acc[mi][ni][hr * 2 + 0];
                    float v1 = acc[mi][ni][hr * 2 + 1];
                    float w0 = __shfl_xor_sync(0xffffffffu, v0, 1);
                    float w1 = __shfl_xor_sync(0xffffffffu, v1, 1);
                    if ((lane & 1) == 0) {
                        const int hl = ((wn + ni * 8) >> 2) + hlq;
                        float gi = v0 + bsS[hl * 4 + 0];
                        float gf = v1 + bsS[hl * 4 + 1];
                        float gg = w0 + bsS[hl * 4 + 2];
                        float go = w1 + bsS[hl * 4 + 3];
                        if (t < szS[rl]) {
                            const __half* xr = xp + (size_t)(stS[rl] + t) * GATES + n0 + hl * 4;
                            uint2 xv = *reinterpret_cast<const uint2*>(xr);
                            __half2 x01 = *reinterpret_cast<__half2*>(&xv.x);
                            __half2 x23 = *reinterpret_cast<__half2*>(&xv.y);
                            gi += __half2float(x01.x);
                            gf += __half2float(x01.y);
                            gg += __half2float(x23.x);
                            go += __half2float(x23.y);
                        }
                        float is = 1.f / (1.f + __expf(-gi));
                        float fs = 1.f / (1.f + __expf(-gf));
                        float gt = tanhf(gg);
                        float os = 1.f / (1.f + __expf(-go));
                        float cn = fs * creg[mi][hr][ni] + is * gt;
                        creg[mi][hr][ni] = cn;
                        hS[rl * 32 + hl] = __float2half(os * tanhf(cn));
                    }
                }
            }
        }
        __syncthreads();
        // coalesced h store: 128 rows x 32 hids (16B chunks)
        for (int i = tid; i < 512; i += 256) {
            int r = i >> 2, ch = i & 3;
            *reinterpret_cast<uint4*>(hN + (size_t)(m0 + r) * HID + (n0 >> 2) + ch * 8) =
                *reinterpret_cast<const uint4*>(&hS[r * 32 + ch * 8]);
        }
        grid_sync_128();
    }
}

// ---------------------------------------------------------------------------
// fp32 tail GEMM + decoder (unchanged)
// ---------------------------------------------------------------------------
#define BM 64
#define BN 64
#define BK 16
__global__ __launch_bounds__(256) void gemm_nt_kernel(
    const float* __restrict__ A, const float* __restrict__ B,
    const float* __restrict__ bias, const float* __restrict__ R,
    float* __restrict__ C, int M, int N, int K)
{
    __shared__ float As[BK][BM];
    __shared__ float Bs[BK][BN];
    const int m0 = blockIdx.y * BM;
    const int n0 = blockIdx.x * BN;
    const int tid = threadIdx.x;
    const int tx = tid & 15, ty = tid >> 4;
    const int lrow = tid >> 2, lkq = (tid & 3) * 4;
    float acc[4][4] = {};
    for (int k0 = 0; k0 < K; k0 += BK) {
        {
            int gm = m0 + lrow;
            float4 v = make_float4(0.f, 0.f, 0.f, 0.f);
            if (gm < M) v = *reinterpret_cast<const float4*>(A + (size_t)gm * K + k0 + lkq);
            As[lkq + 0][lrow] = v.x; As[lkq + 1][lrow] = v.y;
            As[lkq + 2][lrow] = v.z; As[lkq + 3][lrow] = v.w;
        }
        {
            float4 v = *reinterpret_cast<const float4*>(B + (size_t)(n0 + lrow) * K + k0 + lkq);
            Bs[lkq + 0][lrow] = v.x; Bs[lkq + 1][lrow] = v.y;
            Bs[lkq + 2][lrow] = v.z; Bs[lkq + 3][lrow] = v.w;
        }
        __syncthreads();
        #pragma unroll
        for (int k = 0; k < BK; k++) {
            float4 a = *reinterpret_cast<const float4*>(&As[k][ty * 4]);
            float4 b = *reinterpret_cast<const float4*>(&Bs[k][tx * 4]);
            acc[0][0] += a.x * b.x; acc[0][1] += a.x * b.y; acc[0][2] += a.x * b.z; acc[0][3] += a.x * b.w;
            acc[1][0] += a.y * b.x; acc[1][1] += a.y * b.y; acc[1][2] += a.y * b.z; acc[1][3] += a.y * b.w;
            acc[2][0] += a.z * b.x; acc[2][1] += a.z * b.y; acc[2][2] += a.z * b.z; acc[2][3] += a.z * b.w;
            acc[3][0] += a.w * b.x; acc[3][1] += a.w * b.y; acc[3][2] += a.w * b.z; acc[3][3] += a.w * b.w;
        }
        __syncthreads();
    }
    #pragma unroll
    for (int i = 0; i < 4; i++) {
        int gm = m0 + ty * 4 + i;
        if (gm >= M) continue;
        #pragma unroll
        for (int j = 0; j < 4; j++) {
            int gn = n0 + tx * 4 + j;
            float v = acc[i][j] + bias[gn];
            v = fmaxf(v, 0.f);
            v += R[(size_t)gm * N + gn];
            C[(size_t)gm * N + gn] = v;
        }
    }
}

__global__ void decoder_kernel(const float* __restrict__ X, const float* __restrict__ Wd,
                               const float* __restrict__ bd, float* __restrict__ out, int B)
{
    int warp = (blockIdx.x * blockDim.x + threadIdx.x) >> 5;
    int lane = threadIdx.x & 31;
    if (warp >= B) return;
    const float4* row = reinterpret_cast<const float4*>(X + (size_t)warp * HID);
    const float4* w = reinterpret_cast<const float4*>(Wd);
    float s = 0.f;
    #pragma unroll
    for (int i = lane; i < HID / 4; i += 32) {
        float4 a = row[i], bw = w[i];
        s += a.x * bw.x + a.y * bw.y + a.z * bw.z + a.w * bw.w;
    }
    #pragma unroll
    for (int o = 16; o > 0; o >>= 1) s += __shfl_down_sync(0xffffffffu, s, o);
    if (lane == 0) out[warp] = s + bd[0];
}

// ---------------------------------------------------------------------------
// Launch
// ---------------------------------------------------------------------------
extern "C" void kernel_launch(void* const* d_in, const int* in_sizes, int n_in,
                              void* d_out, int out_size)
{
    const int*   sizes = (const int*)  d_in[0];
    const float* feat  = (const float*)d_in[1];
    const float* We0   = (const float*)d_in[2];
    const float* be0   = (const float*)d_in[3];
    const float* We1   = (const float*)d_in[4];
    const float* be1   = (const float*)d_in[5];
    const float* Wih   = (const float*)d_in[6];
    const float* bih   = (const float*)d_in[7];
    const float* Whh   = (const float*)d_in[8];
    const float* bhh   = (const float*)d_in[9];
    const float* Wl0   = (const float*)d_in[10];
    const float* bl0   = (const float*)d_in[11];
    const float* Wl1   = (const float*)d_in[12];
    const float* bl1   = (const float*)d_in[13];
    const float* Wd    = (const float*)d_in[14];
    const float* bd    = (const float*)d_in[15];

    const int B  = in_sizes[0];
    const int K0 = in_sizes[2] / HID;
    const int T  = in_sizes[1] / K0;

    __half *feat16, *x1h, *x2h, *xp16, *We0h, *We1h, *Wihp, *Whhp, *h0, *h1;
    float *bsum, *hf, *t0, *t1;
    int *starts;
    cudaGetSymbolAddress((void**)&feat16, g_feat16);
    cudaGetSymbolAddress((void**)&x1h,   g_x1h);
    cudaGetSymbolAddress((void**)&x2h,   g_x2h);
    cudaGetSymbolAddress((void**)&xp16,  g_xp16);
    cudaGetSymbolAddress((void**)&We0h,  g_We0h);
    cudaGetSymbolAddress((void**)&We1h,  g_We1h);
    cudaGetSymbolAddress((void**)&Wihp,  g_Wihp);
    cudaGetSymbolAddress((void**)&Whhp,  g_Whhp);
    cudaGetSymbolAddress((void**)&bsum,  g_bsum);
    cudaGetSymbolAddress((void**)&h0,    g_h0);
    cudaGetSymbolAddress((void**)&h1,    g_h1);
    cudaGetSymbolAddress((void**)&hf,    g_hf);
    cudaGetSymbolAddress((void**)&t0,    g_t0);
    cudaGetSymbolAddress((void**)&t1,    g_t1);
    cudaGetSymbolAddress((void**)&starts, g_starts);

    cudaFuncSetAttribute(lstm_persist, cudaFuncAttributeMaxDynamicSharedMemorySize, LSTM_SMEM);

    scan_starts_kernel<<<1, BMAX>>>(sizes, starts, B);

    // conversions / permutations
    {
        int n = T * K0PAD;
        f2h_pad<<<(n + 255) / 256, 256>>>(feat, feat16, T, K0, K0PAD);
        n = HID * K0PAD;
        f2h_pad<<<(n + 255) / 256, 256>>>(We0, We0h, HID, K0, K0PAD);
        n = HID * HID;
        f2h_pad<<<(n + 255) / 256, 256>>>(We1, We1h, HID, HID, HID);
        perm_rows_h<<<(GATES * HID + 255) / 256, 256>>>(Wih, Wihp);
        perm_rows_h<<<(GATES * HID + 255) / 256, 256>>>(Whh, Whhp);
        bsum_kernel<<<(GATES + 255) / 256, 256>>>(bih, bhh, bsum);
    }
    fill_zero_h<<<(B * HID + 255) / 256, 256>>>(h0, B * HID);

    const int mblkT = (T + 127) / 128;
    // encoder
    hgemm_nt<true, true><<<dim3(HID / 128, mblkT), 256>>>(feat16, We0h, be0, x1h, T, HID, K0PAD);
    hgemm_nt<true, true><<<dim3(HID / 128, mblkT), 256>>>(x1h, We1h, be1, x2h, T, HID, HID);
    // xproj (gate-interleaved columns via permuted Wih rows)
    hgemm_nt<false, false><<<dim3(GATES / 128, mblkT), 256>>>(x2h, Wihp, nullptr, xp16, T, GATES, HID);

    // persistent LSTM: all 128 steps in one kernel
    lstm_persist<<<NCTA, 256, LSTM_SMEM>>>(Whhp, xp16, bsum, starts, sizes, h0, h1);

    // final h (t=127 wrote hbuf0) -> fp32, tail
    h2f_kernel<<<(B * HID + 255) / 256, 256>>>(h0, hf, B * HID);
    gemm_nt_kernel<<<dim3(HID / BN, B / BM), 256>>>(hf, Wl0, bl0, hf, t0, B, HID, HID);
    gemm_nt_kernel<<<dim3(HID / BN, B / BM), 256>>>(t0, Wl1, bl1, t0, t1, B, HID, HID);
    decoder_kernel<<<(B * 32 + 255) / 256, 256>>>(t1, Wd, bd, (float*)d_out, B);
}

// round 6
// speedup vs baseline: 4.4488x; 1.1882x over previous
#include <cuda_runtime.h>
#include <cuda_fp16.h>
#include <math.h>
#include <stdint.h>

// ---------------------------------------------------------------------------
// Problem constants
// ---------------------------------------------------------------------------
#define HID    512
#define GATES  2048
#define MAXLEN 128
#define BMAX   1024
#define TMAX   (BMAX * 127)
#define K0PAD  192
#define NCTA   128         // persistent LSTM grid (16 nblk x 8 mblk)
#define NGRP   8           // barrier groups (one per mblk)
#define GRPSZ  16          // CTAs per group

// ---------------------------------------------------------------------------
// Scratch
// ---------------------------------------------------------------------------
__device__ __half g_feat16[(size_t)TMAX * K0PAD];
__device__ __half g_x1h  [(size_t)TMAX * HID];
__device__ __half g_x2h  [(size_t)TMAX * HID];
__device__ __half g_xp16 [(size_t)TMAX * GATES];
__device__ __half g_We0h [HID * K0PAD];
__device__ __half g_We1h [HID * HID];
__device__ __half g_Wihp [GATES * HID];     // gate-interleaved rows
__device__ __half g_Whhp [GATES * HID];     // gate-interleaved rows
__device__ float  g_bsum [GATES];           // gate-interleaved bih+bhh
__device__ __half g_h0   [BMAX * HID];
__device__ __half g_h1   [BMAX * HID];
__device__ float  g_hf   [BMAX * HID];
__device__ float  g_t0   [BMAX * HID];
__device__ float  g_t1   [BMAX * HID];
__device__ int    g_starts[BMAX];
// per-group barrier state, padded to separate 128B L2 lines
__device__ unsigned          g_cnt8[NGRP][32];
__device__ volatile unsigned g_gen8[NGRP][32];

// ---------------------------------------------------------------------------
// Helpers
// ---------------------------------------------------------------------------
__device__ __forceinline__ uint32_t smem_u32(const void* p) {
    return (uint32_t)__cvta_generic_to_shared(p);
}
__device__ __forceinline__ void cp_async16(void* dst, const void* src, bool pred) {
    uint32_t d = smem_u32(dst);
    int sz = pred ? 16 : 0;
    asm volatile("cp.async.cg.shared.global [%0], [%1], 16, %2;\n"
                 :: "r"(d), "l"(src), "r"(sz));
}
__device__ __forceinline__ void cp_commit() { asm volatile("cp.async.commit_group;\n"); }
template<int N> __device__ __forceinline__ void cp_wait() {
    asm volatile("cp.async.wait_group %0;\n" :: "n"(N));
}
__device__ __forceinline__ void ldm_x4(uint32_t addr, uint32_t& r0, uint32_t& r1,
                                       uint32_t& r2, uint32_t& r3) {
    asm volatile("ldmatrix.sync.aligned.m8n8.x4.shared.b16 {%0,%1,%2,%3}, [%4];"
                 : "=r"(r0), "=r"(r1), "=r"(r2), "=r"(r3) : "r"(addr));
}
__device__ __forceinline__ void mma16816(float* c, const uint32_t* a, const uint32_t* b) {
    asm volatile("mma.sync.aligned.m16n8k16.row.col.f32.f16.f16.f32 "
                 "{%0,%1,%2,%3}, {%4,%5,%6,%7}, {%8,%9}, {%0,%1,%2,%3};"
                 : "+f"(c[0]), "+f"(c[1]), "+f"(c[2]), "+f"(c[3])
                 : "r"(a[0]), "r"(a[1]), "r"(a[2]), "r"(a[3]), "r"(b[0]), "r"(b[1]));
}

// ---------------------------------------------------------------------------
// setup kernels
// ---------------------------------------------------------------------------
__global__ void scan_starts_kernel(const int* __restrict__ sizes, int* __restrict__ starts, int B) {
    __shared__ int s[BMAX];
    int tid = threadIdx.x;
    if (tid < B) s[tid] = sizes[tid];
    __syncthreads();
    if (tid == 0) {
        int acc = 0;
        for (int i = 0; i < B; i++) { starts[i] = acc; acc += s[i]; }
    }
}
__global__ void fill_zero_h(__half* __restrict__ p, int n) {
    int i = blockIdx.x * blockDim.x + threadIdx.x;
    if (i < n) p[i] = __float2half(0.f);
}
__global__ void f2h_pad(const float* __restrict__ src, __half* __restrict__ dst,
                        int R, int C, int Cp) {
    int i = blockIdx.x * blockDim.x + threadIdx.x;
    if (i >= R * Cp) return;
    int r = i / Cp, c = i - r * Cp;
    dst[i] = __float2half(c < C ? src[(size_t)r * C + c] : 0.f);
}
// permute rows g*512+hid -> hid*4+g, fp32->fp16  (W is [2048][512])
__global__ void perm_rows_h(const float* __restrict__ w, __half* __restrict__ dst) {
    int i = blockIdx.x * blockDim.x + threadIdx.x;
    if (i >= GATES * HID) return;
    int r = i >> 9, c = i & 511;
    int g = r >> 9, hid = r & 511;
    dst[(size_t)(hid * 4 + g) * HID + c] = __float2half(w[i]);
}
__global__ void bsum_kernel(const float* __restrict__ bih, const float* __restrict__ bhh,
                            float* __restrict__ bsum) {
    int o = blockIdx.x * blockDim.x + threadIdx.x;
    if (o >= GATES) return;
    int hid = o >> 2, g = o & 3;
    bsum[o] = bih[g * HID + hid] + bhh[g * HID + hid];
}
__global__ void h2f_kernel(const __half* __restrict__ src, float* __restrict__ dst, int n) {
    int i = blockIdx.x * blockDim.x + threadIdx.x;
    if (i < n) dst[i] = __half2float(src[i]);
}

// ---------------------------------------------------------------------------
// fp16 NT GEMM (encoder / xproj) — now 2 CTAs/SM for latency hiding
// ---------------------------------------------------------------------------
template<bool RELU, bool HAS_BIAS>
__global__ __launch_bounds__(256, 2)
void hgemm_nt(const __half* __restrict__ A, const __half* __restrict__ B,
              const float* __restrict__ bias, __half* __restrict__ Cout,
              int M, int N, int K)
{
    __shared__ __half As[2][128][40];
    __shared__ __half Bs[2][128][40];

    const int m0 = blockIdx.y * 128;
    const int n0 = blockIdx.x * 128;
    const int tid = threadIdx.x;
    const int warp = tid >> 5, lane = tid & 31;
    const int wm = (warp & 3) * 32;
    const int wn = (warp >> 2) * 64;

    float acc[2][8][4];
    #pragma unroll
    for (int i = 0; i < 2; i++)
        #pragma unroll
        for (int j = 0; j < 8; j++)
            #pragma unroll
            for (int q = 0; q < 4; q++) acc[i][j][q] = 0.f;

    const int KT = K >> 5;
    const int lrow = tid >> 1;

    {
        #pragma unroll
        for (int i = 0; i < 2; i++) {
            int col = ((tid & 1) * 2 + i) * 8;
            int gm = m0 + lrow;
            bool p = gm < M;
            cp_async16(&As[0][lrow][col], A + (size_t)(p ? gm : 0) * K + col, p);
        }
        #pragma unroll
        for (int i = 0; i < 2; i++) {
            int col = ((tid & 1) * 2 + i) * 8;
            cp_async16(&Bs[0][lrow][col], B + (size_t)(n0 + lrow) * K + col, true);
        }
        cp_commit();
    }

    for (int kt = 0; kt < KT; kt++) {
        const int buf = kt & 1;
        if (kt + 1 < KT) {
            const int k0 = (kt + 1) << 5;
            #pragma unroll
            for (int i = 0; i < 2; i++) {
                int col = ((tid & 1) * 2 + i) * 8;
                int gm = m0 + lrow;
                bool p = gm < M;
                cp_async16(&As[buf ^ 1][lrow][col], A + (size_t)(p ? gm : 0) * K + k0 + col, p);
            }
            #pragma unroll
            for (int i = 0; i < 2; i++) {
                int col = ((tid & 1) * 2 + i) * 8;
                cp_async16(&Bs[buf ^ 1][lrow][col], B + (size_t)(n0 + lrow) * K + k0 + col, true);
            }
            cp_commit();
            cp_wait<1>();
        } else {
            cp_wait<0>();
        }
        __syncthreads();

        #pragma unroll
        for (int s = 0; s < 2; s++) {
            uint32_t afrag[2][4];
            #pragma unroll
            for (int mi = 0; mi < 2; mi++) {
                int r = wm + mi * 16 + (lane & 15);
                int c = s * 16 + (lane >> 4) * 8;
                ldm_x4(smem_u32(&As[buf][r][c]),
                       afrag[mi][0], afrag[mi][1], afrag[mi][2], afrag[mi][3]);
            }
            uint32_t bfrag[8][2];
            #pragma unroll
            for (int njp = 0; njp < 4; njp++) {
                int g = lane >> 3;
                int nrow = wn + njp * 16 + (g >> 1) * 8 + (lane & 7);
                int c = s * 16 + (g & 1) * 8;
                uint32_t r0, r1, r2, r3;
                ldm_x4(smem_u32(&Bs[buf][nrow][c]), r0, r1, r2, r3);
                bfrag[njp * 2][0] = r0; bfrag[njp * 2][1] = r1;
                bfrag[njp * 2 + 1][0] = r2; bfrag[njp * 2 + 1][1] = r3;
            }
            #pragma unroll
            for (int mi = 0; mi < 2; mi++)
                #pragma unroll
                for (int ni = 0; ni < 8; ni++)
                    mma16816(acc[mi][ni], afrag[mi], bfrag[ni]);
        }
        __syncthreads();
    }

    const int r_lo = lane >> 2;
    const int cpair = (lane & 3) * 2;
    #pragma unroll
    for (int mi = 0; mi < 2; mi++) {
        #pragma unroll
        for (int hr = 0; hr < 2; hr++) {
            int gr = m0 + wm + mi * 16 + r_lo + hr * 8;
            if (gr >= M) continue;
            #pragma unroll
            for (int ni = 0; ni < 8; ni++) {
                int gc = n0 + wn + ni * 8 + cpair;
                float v0 = acc[mi][ni][hr * 2 + 0];
                float v1 = acc[mi][ni][hr * 2 + 1];
                if (HAS_BIAS) { v0 += bias[gc]; v1 += bias[gc + 1]; }
                if (RELU) { v0 = fmaxf(v0, 0.f); v1 = fmaxf(v1, 0.f); }
                __half2 hv;
                hv.x = __float2half(v0); hv.y = __float2half(v1);
                *reinterpret_cast<__half2*>(Cout + (size_t)gr * N + gc) = hv;
            }
        }
    }
}

// ---------------------------------------------------------------------------
// Persistent LSTM kernel. Grid = 128 CTAs (16 nblk x 8 mblk), 256 threads.
// Whh resident in smem; c in registers; per-mblk-group (16 CTA) barriers;
// xproj slice prefetched to smem during the MMA loop.
// ---------------------------------------------------------------------------
// dyn smem layout (bytes):
//   WhS    [128][520] half : 0      .. 133120
//   AS [2] [128][40]  half : 133120 .. 153600
//   xpS    [128][128] half : 153600 .. 186368
//   bsS    [128] float     : 186368 .. 186880
//   stS    [128] int       : 186880 .. 187392
//   szS    [128] int       : 187392 .. 187904
//   hS     [128][32] half  : 187904 .. 196096
#define LSTM_SMEM 196096

__device__ __forceinline__ void group_sync(int grp) {
    __syncthreads();
    if (threadIdx.x == 0) {
        __threadfence();
        unsigned gen = g_gen8[grp][0];
        if (atomicAdd(&g_cnt8[grp][0], 1) == GRPSZ - 1) {
            g_cnt8[grp][0] = 0;
            __threadfence();
            g_gen8[grp][0] = gen + 1;
        } else {
            while (g_gen8[grp][0] == gen) { __nanosleep(20); }
        }
    }
    __syncthreads();
}

__global__ __launch_bounds__(256, 1)
void lstm_persist(const __half* __restrict__ Whp, const __half* __restrict__ xp,
                  const float* __restrict__ bsum,
                  const int* __restrict__ starts, const int* __restrict__ sizes,
                  __half* __restrict__ hbuf0, __half* __restrict__ hbuf1)
{
    extern __shared__ char smem[];
    __half* WhS = (__half*)(smem);
    __half* AS  = (__half*)(smem + 133120);   // [2][128][40]
    __half* xpS = (__half*)(smem + 153600);   // [128][128]
    float*  bsS = (float*) (smem + 186368);
    int*    stS = (int*)   (smem + 186880);
    int*    szS = (int*)   (smem + 187392);
    __half* hS  = (__half*)(smem + 187904);   // [128][32]

    const int tid  = threadIdx.x;
    const int warp = tid >> 5, lane = tid & 31;
    const int nblk = blockIdx.x & 15, mblk = blockIdx.x >> 4;
    const int n0 = nblk * 128, m0 = mblk * 128;
    const int wm = (warp & 3) * 32, wn = (warp >> 2) * 64;
    const int lrow = tid >> 1;

    // ---- load resident Whh slice (gate-interleaved rows n0..n0+127) ----
    for (int i = tid; i < 128 * 64; i += 256) {
        int r = i >> 6, ch = i & 63;
        cp_async16(&WhS[r * 520 + ch * 8], Whp + (size_t)(n0 + r) * HID + ch * 8, true);
    }
    cp_commit();
    for (int i = tid; i < 128; i += 256) {
        bsS[i] = bsum[n0 + i];
        stS[i] = starts[m0 + i];
        szS[i] = sizes[m0 + i];
    }
    cp_wait<0>();
    __syncthreads();

    // c state in registers (even lanes hold the real values)
    float creg[2][2][8];
    #pragma unroll
    for (int mi = 0; mi < 2; mi++)
        #pragma unroll
        for (int hr = 0; hr < 2; hr++)
            #pragma unroll
            for (int ni = 0; ni < 8; ni++) creg[mi][hr][ni] = 0.f;

    for (int t = 0; t < MAXLEN; t++) {
        const __half* hA = (t & 1) ? hbuf1 : hbuf0;
        __half*       hN = (t & 1) ? hbuf0 : hbuf1;

        // prologue: A tile 0
        #pragma unroll
        for (int i = 0; i < 2; i++) {
            int col = ((tid & 1) * 2 + i) * 8;
            cp_async16(&AS[lrow * 40 + col], hA + (size_t)(m0 + lrow) * HID + col, true);
        }
        cp_commit();

        float acc[2][8][4];
        #pragma unroll
        for (int mi = 0; mi < 2; mi++)
            #pragma unroll
            for (int ni = 0; ni < 8; ni++)
                #pragma unroll
                for (int q = 0; q < 4; q++) acc[mi][ni][q] = 0.f;

        for (int kt = 0; kt < 16; kt++) {
            const int buf = kt & 1;
            if (kt < 15) {
                const int k0 = (kt + 1) << 5;
                #pragma unroll
                for (int i = 0; i < 2; i++) {
                    int col = ((tid & 1) * 2 + i) * 8;
                    cp_async16(&AS[(buf ^ 1) * 5120 + lrow * 40 + col],
                               hA + (size_t)(m0 + lrow) * HID + k0 + col, true);
                }
                if (kt == 0) {
                    // prefetch this step's xproj slice (rides in chunk-1's group):
                    // 128 rows x 128 gate-cols (n0..n0+127) = 2048 x 16B
                    for (int i = tid; i < 2048; i += 256) {
                        int rl = i >> 4, ch = i & 15;
                        bool pv = t < szS[rl];
                        const __half* src = xp + (size_t)(stS[rl] + t) * GATES + n0 + ch * 8;
                        cp_async16(&xpS[rl * 128 + ch * 8], src, pv);
                    }
                }
                cp_commit();
                cp_wait<1>();
            } else {
                cp_wait<0>();
            }
            __syncthreads();

            #pragma unroll
            for (int s = 0; s < 2; s++) {
                const int ks = kt * 2 + s;
                uint32_t afrag[2][4];
                #pragma unroll
                for (int mi = 0; mi < 2; mi++) {
                    int r = wm + mi * 16 + (lane & 15);
                    int c = s * 16 + (lane >> 4) * 8;
                    ldm_x4(smem_u32(&AS[buf * 5120 + r * 40 + c]),
                           afrag[mi][0], afrag[mi][1], afrag[mi][2], afrag[mi][3]);
                }
                uint32_t bfrag[8][2];
                #pragma unroll
                for (int njp = 0; njp < 4; njp++) {
                    int g = lane >> 3;
                    int nrow = wn + njp * 16 + (g >> 1) * 8 + (lane & 7);
                    int c = ks * 16 + (g & 1) * 8;
                    uint32_t r0, r1, r2, r3;
                    ldm_x4(smem_u32(&WhS[nrow * 520 + c]), r0, r1, r2, r3);
                    bfrag[njp * 2][0] = r0; bfrag[njp * 2][1] = r1;
                    bfrag[njp * 2 + 1][0] = r2; bfrag[njp * 2 + 1][1] = r3;
                }
                #pragma unroll
                for (int mi = 0; mi < 2; mi++)
                    #pragma unroll
                    for (int ni = 0; ni < 8; ni++)
                        mma16816(acc[mi][ni], afrag[mi], bfrag[ni]);
            }
            __syncthreads();
        }

        // ---- fused LSTM epilogue (xproj now read from smem) ----
        const int hlq = (lane & 3) >> 1;
        const int rbase = wm + (lane >> 2);
        #pragma unroll
        for (int mi = 0; mi < 2; mi++) {
            #pragma unroll
            for (int hr = 0; hr < 2; hr++) {
                const int rl = rbase + mi * 16 + hr * 8;   // local batch row
                #pragma unroll
                for (int ni = 0; ni < 8; ni++) {
                    float v0 = acc[mi][ni][hr * 2 + 0];
                    float v1 = acc[mi][ni][hr * 2 + 1];
                    float w0 = __shfl_xor_sync(0xffffffffu, v0, 1);
                    float w1 = __shfl_xor_sync(0xffffffffu, v1, 1);
                    if ((lane & 1) == 0) {
                        const int hl = ((wn + ni * 8) >> 2) + hlq;
                        float gi = v0 + bsS[hl * 4 + 0];
                        float gf = v1 + bsS[hl * 4 + 1];
                        float gg = w0 + bsS[hl * 4 + 2];
                        float go = w1 + bsS[hl * 4 + 3];
                        if (t < szS[rl]) {
                            uint2 xv = *reinterpret_cast<const uint2*>(&xpS[rl * 128 + hl * 4]);
                            __half2 x01 = *reinterpret_cast<__half2*>(&xv.x);
                            __half2 x23 = *reinterpret_cast<__half2*>(&xv.y);
                            gi += __half2float(x01.x);
                            gf += __half2float(x01.y);
                            gg += __half2float(x23.x);
                            go += __half2float(x23.y);
                        }
                        float is = 1.f / (1.f + __expf(-gi));
                        float fs = 1.f / (1.f + __expf(-gf));
                        float gt = tanhf(gg);
                        float os = 1.f / (1.f + __expf(-go));
                        float cn = fs * creg[mi][hr][ni] + is * gt;
                        creg[mi][hr][ni] = cn;
                        hS[rl * 32 + hl] = __float2half(os * tanhf(cn));
                    }
                }
            }
        }
        __syncthreads();
        // coalesced h store: 128 rows x 32 hids (16B chunks)
        for (int i = tid; i < 512; i += 256) {
            int r = i >> 2, ch = i & 3;
            *reinterpret_cast<uint4*>(hN + (size_t)(m0 + r) * HID + (n0 >> 2) + ch * 8) =
                *reinterpret_cast<const uint4*>(&hS[r * 32 + ch * 8]);
        }
        // only CTAs sharing this mblk depend on each other
        group_sync(mblk);
    }
}

// ---------------------------------------------------------------------------
// fp32 tail GEMM + decoder
// ---------------------------------------------------------------------------
#define BM 64
#define BN 64
#define BK 16
__global__ __launch_bounds__(256) void gemm_nt_kernel(
    const float* __restrict__ A, const float* __restrict__ B,
    const float* __restrict__ bias, const float* __restrict__ R,
    float* __restrict__ C, int M, int N, int K)
{
    __shared__ float As[BK][BM];
    __shared__ float Bs[BK][BN];
    const int m0 = blockIdx.y * BM;
    const int n0 = blockIdx.x * BN;
    const int tid = threadIdx.x;
    const int tx = tid & 15, ty = tid >> 4;
    const int lrow = tid >> 2, lkq = (tid & 3) * 4;
    float acc[4][4] = {};
    for (int k0 = 0; k0 < K; k0 += BK) {
        {
            int gm = m0 + lrow;
            float4 v = make_float4(0.f, 0.f, 0.f, 0.f);
            if (gm < M) v = *reinterpret_cast<const float4*>(A + (size_t)gm * K + k0 + lkq);
            As[lkq + 0][lrow] = v.x; As[lkq + 1][lrow] = v.y;
            As[lkq + 2][lrow] = v.z; As[lkq + 3][lrow] = v.w;
        }
        {
            float4 v = *reinterpret_cast<const float4*>(B + (size_t)(n0 + lrow) * K + k0 + lkq);
            Bs[lkq + 0][lrow] = v.x; Bs[lkq + 1][lrow] = v.y;
            Bs[lkq + 2][lrow] = v.z; Bs[lkq + 3][lrow] = v.w;
        }
        __syncthreads();
        #pragma unroll
        for (int k = 0; k < BK; k++) {
            float4 a = *reinterpret_cast<const float4*>(&As[k][ty * 4]);
            float4 b = *reinterpret_cast<const float4*>(&Bs[k][tx * 4]);
            acc[0][0] += a.x * b.x; acc[0][1] += a.x * b.y; acc[0][2] += a.x * b.z; acc[0][3] += a.x * b.w;
            acc[1][0] += a.y * b.x; acc[1][1] += a.y * b.y; acc[1][2] += a.y * b.z; acc[1][3] += a.y * b.w;
            acc[2][0] += a.z * b.x; acc[2][1] += a.z * b.y; acc[2][2] += a.z * b.z; acc[2][3] += a.z * b.w;
            acc[3][0] += a.w * b.x; acc[3][1] += a.w * b.y; acc[3][2] += a.w * b.z; acc[3][3] += a.w * b.w;
        }
        __syncthreads();
    }
    #pragma unroll
    for (int i = 0; i < 4; i++) {
        int gm = m0 + ty * 4 + i;
        if (gm >= M) continue;
        #pragma unroll
        for (int j = 0; j < 4; j++) {
            int gn = n0 + tx * 4 + j;
            float v = acc[i][j] + bias[gn];
            v = fmaxf(v, 0.f);
            v += R[(size_t)gm * N + gn];
            C[(size_t)gm * N + gn] = v;
        }
    }
}

__global__ void decoder_kernel(const float* __restrict__ X, const float* __restrict__ Wd,
                               const float* __restrict__ bd, float* __restrict__ out, int B)
{
    int warp = (blockIdx.x * blockDim.x + threadIdx.x) >> 5;
    int lane = threadIdx.x & 31;
    if (warp >= B) return;
    const float4* row = reinterpret_cast<const float4*>(X + (size_t)warp * HID);
    const float4* w = reinterpret_cast<const float4*>(Wd);
    float s = 0.f;
    #pragma unroll
    for (int i = lane; i < HID / 4; i += 32) {
        float4 a = row[i], bw = w[i];
        s += a.x * bw.x + a.y * bw.y + a.z * bw.z + a.w * bw.w;
    }
    #pragma unroll
    for (int o = 16; o > 0; o >>= 1) s += __shfl_down_sync(0xffffffffu, s, o);
    if (lane == 0) out[warp] = s + bd[0];
}

// ---------------------------------------------------------------------------
// Launch
// ---------------------------------------------------------------------------
extern "C" void kernel_launch(void* const* d_in, const int* in_sizes, int n_in,
                              void* d_out, int out_size)
{
    const int*   sizes = (const int*)  d_in[0];
    const float* feat  = (const float*)d_in[1];
    const float* We0   = (const float*)d_in[2];
    const float* be0   = (const float*)d_in[3];
    const float* We1   = (const float*)d_in[4];
    const float* be1   = (const float*)d_in[5];
    const float* Wih   = (const float*)d_in[6];
    const float* bih   = (const float*)d_in[7];
    const float* Whh   = (const float*)d_in[8];
    const float* bhh   = (const float*)d_in[9];
    const float* Wl0   = (const float*)d_in[10];
    const float* bl0   = (const float*)d_in[11];
    const float* Wl1   = (const float*)d_in[12];
    const float* bl1   = (const float*)d_in[13];
    const float* Wd    = (const float*)d_in[14];
    const float* bd    = (const float*)d_in[15];

    const int B  = in_sizes[0];
    const int K0 = in_sizes[2] / HID;
    const int T  = in_sizes[1] / K0;

    __half *feat16, *x1h, *x2h, *xp16, *We0h, *We1h, *Wihp, *Whhp, *h0, *h1;
    float *bsum, *hf, *t0, *t1;
    int *starts;
    cudaGetSymbolAddress((void**)&feat16, g_feat16);
    cudaGetSymbolAddress((void**)&x1h,   g_x1h);
    cudaGetSymbolAddress((void**)&x2h,   g_x2h);
    cudaGetSymbolAddress((void**)&xp16,  g_xp16);
    cudaGetSymbolAddress((void**)&We0h,  g_We0h);
    cudaGetSymbolAddress((void**)&We1h,  g_We1h);
    cudaGetSymbolAddress((void**)&Wihp,  g_Wihp);
    cudaGetSymbolAddress((void**)&Whhp,  g_Whhp);
    cudaGetSymbolAddress((void**)&bsum,  g_bsum);
    cudaGetSymbolAddress((void**)&h0,    g_h0);
    cudaGetSymbolAddress((void**)&h1,    g_h1);
    cudaGetSymbolAddress((void**)&hf,    g_hf);
    cudaGetSymbolAddress((void**)&t0,    g_t0);
    cudaGetSymbolAddress((void**)&t1,    g_t1);
    cudaGetSymbolAddress((void**)&starts, g_starts);

    cudaFuncSetAttribute(lstm_persist, cudaFuncAttributeMaxDynamicSharedMemorySize, LSTM_SMEM);

    scan_starts_kernel<<<1, BMAX>>>(sizes, starts, B);

    // conversions / permutations
    {
        int n = T * K0PAD;
        f2h_pad<<<(n + 255) / 256, 256>>>(feat, feat16, T, K0, K0PAD);
        n = HID * K0PAD;
        f2h_pad<<<(n + 255) / 256, 256>>>(We0, We0h, HID, K0, K0PAD);
        n = HID * HID;
        f2h_pad<<<(n + 255) / 256, 256>>>(We1, We1h, HID, HID, HID);
        perm_rows_h<<<(GATES * HID + 255) / 256, 256>>>(Wih, Wihp);
        perm_rows_h<<<(GATES * HID + 255) / 256, 256>>>(Whh, Whhp);
        bsum_kernel<<<(GATES + 255) / 256, 256>>>(bih, bhh, bsum);
    }
    fill_zero_h<<<(B * HID + 255) / 256, 256>>>(h0, B * HID);

    const int mblkT = (T + 127) / 128;
    // encoder
    hgemm_nt<true, true><<<dim3(HID / 128, mblkT), 256>>>(feat16, We0h, be0, x1h, T, HID, K0PAD);
    hgemm_nt<true, true><<<dim3(HID / 128, mblkT), 256>>>(x1h, We1h, be1, x2h, T, HID, HID);
    // xproj (gate-interleaved columns via permuted Wih rows)
    hgemm_nt<false, false><<<dim3(GATES / 128, mblkT), 256>>>(x2h, Wihp, nullptr, xp16, T, GATES, HID);

    // persistent LSTM: all 128 steps in one kernel
    lstm_persist<<<NCTA, 256, LSTM_SMEM>>>(Whhp, xp16, bsum, starts, sizes, h0, h1);

    // final h (t=127 wrote hbuf0) -> fp32, tail
    h2f_kernel<<<(B * HID + 255) / 256, 256>>>(h0, hf, B * HID);
    gemm_nt_kernel<<<dim3(HID / BN, B / BM), 256>>>(hf, Wl0, bl0, hf, t0, B, HID, HID);
    gemm_nt_kernel<<<dim3(HID / BN, B / BM), 256>>>(t0, Wl1, bl1, t0, t1, B, HID, HID);
    decoder_kernel<<<(B * 32 + 255) / 256, 256>>>(t1, Wd, bd, (float*)d_out, B);
}

// round 7
// speedup vs baseline: 4.8435x; 1.0887x over previous
#include <cuda_runtime.h>
#include <cuda_fp16.h>
#include <math.h>
#include <stdint.h>

// ---------------------------------------------------------------------------
// Problem constants
// ---------------------------------------------------------------------------
#define HID    512
#define GATES  2048
#define MAXLEN 128
#define BMAX   1024
#define TMAX   (BMAX * 127)
#define K0PAD  192
#define NCTA   128         // persistent LSTM grid (16 nblk x 8 mblk)
#define NGRP   8
#define GRPSZ  16

// LSTM kernel chunking
#define CH        64                 // A-chunk columns
#define NKT       8                  // chunks per step (512/64)
#define AS_STRIDE 72                 // 64 + 8 pad halves
#define AS_STAGE  (128 * AS_STRIDE)  // halves per stage

// ---------------------------------------------------------------------------
// Scratch
// ---------------------------------------------------------------------------
__device__ __half g_feat16[(size_t)TMAX * K0PAD];
__device__ __half g_x1h  [(size_t)TMAX * HID];
__device__ __half g_x2h  [(size_t)TMAX * HID];
__device__ __half g_xp16 [(size_t)TMAX * GATES];
__device__ __half g_We0h [HID * K0PAD];
__device__ __half g_We1h [HID * HID];
__device__ __half g_Wihp [GATES * HID];     // gate-interleaved rows
__device__ __half g_Whhp [GATES * HID];     // gate-interleaved rows
__device__ float  g_bsum [GATES];           // gate-interleaved bih+bhh
__device__ __half g_h0   [BMAX * HID];
__device__ __half g_h1   [BMAX * HID];
__device__ float  g_hf   [BMAX * HID];
__device__ float  g_t0   [BMAX * HID];
__device__ float  g_t1   [BMAX * HID];
__device__ int    g_starts[BMAX];
// per-group barrier state on separate 128B lines
__device__ unsigned          g_cnt8[NGRP][32];
__device__ volatile unsigned g_gen8[NGRP][32];

// ---------------------------------------------------------------------------
// Helpers
// ---------------------------------------------------------------------------
__device__ __forceinline__ uint32_t smem_u32(const void* p) {
    return (uint32_t)__cvta_generic_to_shared(p);
}
__device__ __forceinline__ void cp_async16(void* dst, const void* src, bool pred) {
    uint32_t d = smem_u32(dst);
    int sz = pred ? 16 : 0;
    asm volatile("cp.async.cg.shared.global [%0], [%1], 16, %2;\n"
                 :: "r"(d), "l"(src), "r"(sz));
}
__device__ __forceinline__ void cp_commit() { asm volatile("cp.async.commit_group;\n"); }
template<int N> __device__ __forceinline__ void cp_wait() {
    asm volatile("cp.async.wait_group %0;\n" :: "n"(N));
}
__device__ __forceinline__ void ldm_x4(uint32_t addr, uint32_t& r0, uint32_t& r1,
                                       uint32_t& r2, uint32_t& r3) {
    asm volatile("ldmatrix.sync.aligned.m8n8.x4.shared.b16 {%0,%1,%2,%3}, [%4];"
                 : "=r"(r0), "=r"(r1), "=r"(r2), "=r"(r3) : "r"(addr));
}
__device__ __forceinline__ void mma16816(float* c, const uint32_t* a, const uint32_t* b) {
    asm volatile("mma.sync.aligned.m16n8k16.row.col.f32.f16.f16.f32 "
                 "{%0,%1,%2,%3}, {%4,%5,%6,%7}, {%8,%9}, {%0,%1,%2,%3};"
                 : "+f"(c[0]), "+f"(c[1]), "+f"(c[2]), "+f"(c[3])
                 : "r"(a[0]), "r"(a[1]), "r"(a[2]), "r"(a[3]), "r"(b[0]), "r"(b[1]));
}

// ---------------------------------------------------------------------------
// setup: scan (launch 1) + merged prep (launch 2)
// ---------------------------------------------------------------------------
__global__ void scan_starts_kernel(const int* __restrict__ sizes, int* __restrict__ starts, int B) {
    __shared__ int s[BMAX];
    int tid = threadIdx.x;
    if (tid < B) s[tid] = sizes[tid];
    __syncthreads();
    if (tid == 0) {
        int acc = 0;
        for (int i = 0; i < B; i++) { starts[i] = acc; acc += s[i]; }
    }
}

// One kernel for every conversion / permutation / fill. Block-range dispatch.
__global__ void prep_kernel(const float* __restrict__ feat,
                            const float* __restrict__ We0, const float* __restrict__ We1,
                            const float* __restrict__ Wih, const float* __restrict__ Whh,
                            const float* __restrict__ bih, const float* __restrict__ bhh,
                            int T, int K0, int nb_feat)
{
    int b = blockIdx.x, tid = threadIdx.x;
    if (b < nb_feat) {                       // feat -> fp16, pad K0 -> 192
        int i = b * 256 + tid;
        if (i < T * K0PAD) {
            int r = i / K0PAD, c = i - r * K0PAD;
            g_feat16[i] = __float2half(c < K0 ? feat[(size_t)r * K0 + c] : 0.f);
        }
        return;
    }
    b -= nb_feat;
    if (b < 384) {                           // We0 pad: 512 x 192
        int i = b * 256 + tid;
        int r = i / K0PAD, c = i - r * K0PAD;
        g_We0h[i] = __float2half(c < K0 ? We0[(size_t)r * K0 + c] : 0.f);
        return;
    }
    b -= 384;
    if (b < 1024) {                          // We1: 512 x 512
        int i = b * 256 + tid;
        g_We1h[i] = __float2half(We1[i]);
        return;
    }
    b -= 1024;
    if (b < 4096) {                          // Wih row permute g*512+hid -> hid*4+g
        int i = b * 256 + tid;
        int r = i >> 9, c = i & 511;
        int g = r >> 9, hid = r & 511;
        g_Wihp[(size_t)(hid * 4 + g) * HID + c] = __float2half(Wih[i]);
        return;
    }
    b -= 4096;
    if (b < 4096) {                          // Whh row permute
        int i = b * 256 + tid;
        int r = i >> 9, c = i & 511;
        int g = r >> 9, hid = r & 511;
        g_Whhp[(size_t)(hid * 4 + g) * HID + c] = __float2half(Whh[i]);
        return;
    }
    b -= 4096;
    if (b < 8) {                             // bsum (gate-interleaved)
        int o = b * 256 + tid;
        int hid = o >> 2, g = o & 3;
        g_bsum[o] = bih[g * HID + hid] + bhh[g * HID + hid];
        return;
    }
    b -= 8;
    {                                        // zero h0: 1024*512 halves, 2048 blocks
        int i = b * 256 + tid;
        g_h0[i] = __float2half(0.f);
    }
}

__global__ void h2f_kernel(const __half* __restrict__ src, float* __restrict__ dst, int n) {
    int i = blockIdx.x * blockDim.x + threadIdx.x;
    if (i < n) dst[i] = __half2float(src[i]);
}

// ---------------------------------------------------------------------------
// fp16 NT GEMM (encoder / xproj), 2 CTAs/SM
// ---------------------------------------------------------------------------
template<bool RELU, bool HAS_BIAS>
__global__ __launch_bounds__(256, 2)
void hgemm_nt(const __half* __restrict__ A, const __half* __restrict__ B,
              const float* __restrict__ bias, __half* __restrict__ Cout,
              int M, int N, int K)
{
    __shared__ __half As[2][128][40];
    __shared__ __half Bs[2][128][40];

    const int m0 = blockIdx.y * 128;
    const int n0 = blockIdx.x * 128;
    const int tid = threadIdx.x;
    const int warp = tid >> 5, lane = tid & 31;
    const int wm = (warp & 3) * 32;
    const int wn = (warp >> 2) * 64;

    float acc[2][8][4];
    #pragma unroll
    for (int i = 0; i < 2; i++)
        #pragma unroll
        for (int j = 0; j < 8; j++)
            #pragma unroll
            for (int q = 0; q < 4; q++) acc[i][j][q] = 0.f;

    const int KT = K >> 5;
    const int lrow = tid >> 1;

    {
        #pragma unroll
        for (int i = 0; i < 2; i++) {
            int col = ((tid & 1) * 2 + i) * 8;
            int gm = m0 + lrow;
            bool p = gm < M;
            cp_async16(&As[0][lrow][col], A + (size_t)(p ? gm : 0) * K + col, p);
        }
        #pragma unroll
        for (int i = 0; i < 2; i++) {
            int col = ((tid & 1) * 2 + i) * 8;
            cp_async16(&Bs[0][lrow][col], B + (size_t)(n0 + lrow) * K + col, true);
        }
        cp_commit();
    }

    for (int kt = 0; kt < KT; kt++) {
        const int buf = kt & 1;
        if (kt + 1 < KT) {
            const int k0 = (kt + 1) << 5;
            #pragma unroll
            for (int i = 0; i < 2; i++) {
                int col = ((tid & 1) * 2 + i) * 8;
                int gm = m0 + lrow;
                bool p = gm < M;
                cp_async16(&As[buf ^ 1][lrow][col], A + (size_t)(p ? gm : 0) * K + k0 + col, p);
            }
            #pragma unroll
            for (int i = 0; i < 2; i++) {
                int col = ((tid & 1) * 2 + i) * 8;
                cp_async16(&Bs[buf ^ 1][lrow][col], B + (size_t)(n0 + lrow) * K + k0 + col, true);
            }
            cp_commit();
            cp_wait<1>();
        } else {
            cp_wait<0>();
        }
        __syncthreads();

        #pragma unroll
        for (int s = 0; s < 2; s++) {
            uint32_t afrag[2][4];
            #pragma unroll
            for (int mi = 0; mi < 2; mi++) {
                int r = wm + mi * 16 + (lane & 15);
                int c = s * 16 + (lane >> 4) * 8;
                ldm_x4(smem_u32(&As[buf][r][c]),
                       afrag[mi][0], afrag[mi][1], afrag[mi][2], afrag[mi][3]);
            }
            uint32_t bfrag[8][2];
            #pragma unroll
            for (int njp = 0; njp < 4; njp++) {
                int g = lane >> 3;
                int nrow = wn + njp * 16 + (g >> 1) * 8 + (lane & 7);
                int c = s * 16 + (g & 1) * 8;
                uint32_t r0, r1, r2, r3;
                ldm_x4(smem_u32(&Bs[buf][nrow][c]), r0, r1, r2, r3);
                bfrag[njp * 2][0] = r0; bfrag[njp * 2][1] = r1;
                bfrag[njp * 2 + 1][0] = r2; bfrag[njp * 2 + 1][1] = r3;
            }
            #pragma unroll
            for (int mi = 0; mi < 2; mi++)
                #pragma unroll
                for (int ni = 0; ni < 8; ni++)
                    mma16816(acc[mi][ni], afrag[mi], bfrag[ni]);
        }
        __syncthreads();
    }

    const int r_lo = lane >> 2;
    const int cpair = (lane & 3) * 2;
    #pragma unroll
    for (int mi = 0; mi < 2; mi++) {
        #pragma unroll
        for (int hr = 0; hr < 2; hr++) {
            int gr = m0 + wm + mi * 16 + r_lo + hr * 8;
            if (gr >= M) continue;
            #pragma unroll
            for (int ni = 0; ni < 8; ni++) {
                int gc = n0 + wn + ni * 8 + cpair;
                float v0 = acc[mi][ni][hr * 2 + 0];
                float v1 = acc[mi][ni][hr * 2 + 1];
                if (HAS_BIAS) { v0 += bias[gc]; v1 += bias[gc + 1]; }
                if (RELU) { v0 = fmaxf(v0, 0.f); v1 = fmaxf(v1, 0.f); }
                __half2 hv;
                hv.x = __float2half(v0); hv.y = __float2half(v1);
                *reinterpret_cast<__half2*>(Cout + (size_t)gr * N + gc) = hv;
            }
        }
    }
}

// ---------------------------------------------------------------------------
// Persistent LSTM. Grid = 128 CTAs (16 nblk x 8 mblk), 256 threads.
// 64-col A chunks, ONE __syncthreads per chunk, xproj prefetch hidden under
// the inter-CTA barrier, chunk-0 issued right after the barrier.
// ---------------------------------------------------------------------------
// dyn smem (bytes):
//   WhS  [128][520] half : 0      .. 133120
//   AS   [2][128][72]    : 133120 .. 169984
//   xpS  [128][128] half : 169984 .. 202752
//   bsS  [128] float     : 202752 .. 203264
//   stS  [128] int       : 203264 .. 203776
//   szS  [128] int       : 203776 .. 204288
//   hS   [128][32] half  : 204288 .. 212480
#define LSTM_SMEM 212480

__device__ __forceinline__ void group_sync(int grp) {
    __syncthreads();
    if (threadIdx.x == 0) {
        __threadfence();
        unsigned gen = g_gen8[grp][0];
        if (atomicAdd(&g_cnt8[grp][0], 1) == GRPSZ - 1) {
            g_cnt8[grp][0] = 0;
            __threadfence();
            g_gen8[grp][0] = gen + 1;
        } else {
            while (g_gen8[grp][0] == gen) { }
        }
    }
    __syncthreads();
}

__global__ __launch_bounds__(256, 1)
void lstm_persist(const __half* __restrict__ Whp, const __half* __restrict__ xp,
                  const float* __restrict__ bsum,
                  const int* __restrict__ starts, const int* __restrict__ sizes,
                  __half* __restrict__ hbuf0, __half* __restrict__ hbuf1)
{
    extern __shared__ char smem[];
    __half* WhS = (__half*)(smem);
    __half* AS  = (__half*)(smem + 133120);
    __half* xpS = (__half*)(smem + 169984);
    float*  bsS = (float*) (smem + 202752);
    int*    stS = (int*)   (smem + 203264);
    int*    szS = (int*)   (smem + 203776);
    __half* hS  = (__half*)(smem + 204288);

    const int tid  = threadIdx.x;
    const int warp = tid >> 5, lane = tid & 31;
    const int nblk = blockIdx.x & 15, mblk = blockIdx.x >> 4;
    const int n0 = nblk * 128, m0 = mblk * 128;
    const int wm = (warp & 3) * 32, wn = (warp >> 2) * 64;

    // resident Whh slice (gate-interleaved rows n0..n0+127)
    for (int i = tid; i < 128 * 64; i += 256) {
        int r = i >> 6, ch = i & 63;
        cp_async16(&WhS[r * 520 + ch * 8], Whp + (size_t)(n0 + r) * HID + ch * 8, true);
    }
    cp_commit();
    for (int i = tid; i < 128; i += 256) {
        bsS[i] = bsum[n0 + i];
        stS[i] = starts[m0 + i];
        szS[i] = sizes[m0 + i];
    }
    cp_wait<0>();
    __syncthreads();

    // c state in registers (even lanes hold real values)
    float creg[2][2][8];
    #pragma unroll
    for (int mi = 0; mi < 2; mi++)
        #pragma unroll
        for (int hr = 0; hr < 2; hr++)
            #pragma unroll
            for (int ni = 0; ni < 8; ni++) creg[mi][hr][ni] = 0.f;

    // prologue prefetch for t=0: xp(0) + A chunk 0 (one commit group)
    for (int i = tid; i < 2048; i += 256) {
        int rl = i >> 4, ch = i & 15;
        bool pv = 0 < szS[rl];
        cp_async16(&xpS[rl * 128 + ch * 8], xp + (size_t)stS[rl] * GATES + n0 + ch * 8, pv);
    }
    for (int i = tid; i < 1024; i += 256) {
        int r = i >> 3, ch = i & 7;
        cp_async16(&AS[r * AS_STRIDE + ch * 8], hbuf0 + (size_t)(m0 + r) * HID + ch * 8, true);
    }
    cp_commit();

    for (int t = 0; t < MAXLEN; t++) {
        const __half* hA = (t & 1) ? hbuf1 : hbuf0;
        __half*       hN = (t & 1) ? hbuf0 : hbuf1;

        float acc[2][8][4];
        #pragma unroll
        for (int mi = 0; mi < 2; mi++)
            #pragma unroll
            for (int ni = 0; ni < 8; ni++)
                #pragma unroll
                for (int q = 0; q < 4; q++) acc[mi][ni][q] = 0.f;

        for (int kt = 0; kt < NKT; kt++) {
            cp_wait<0>();
            __syncthreads();    // publish stage kt&1; also: all warps done with chunk kt-1
            if (kt < NKT - 1) {
                const int k0 = (kt + 1) * CH;
                const int stg = (kt + 1) & 1;
                for (int i = tid; i < 1024; i += 256) {
                    int r = i >> 3, ch = i & 7;
                    cp_async16(&AS[stg * AS_STAGE + r * AS_STRIDE + ch * 8],
                               hA + (size_t)(m0 + r) * HID + k0 + ch * 8, true);
                }
                cp_commit();
            }
            const int stage = kt & 1;
            #pragma unroll
            for (int s = 0; s < 4; s++) {
                const int ks = kt * 4 + s;
                uint32_t afrag[2][4];
                #pragma unroll
                for (int mi = 0; mi < 2; mi++) {
                    int r = wm + mi * 16 + (lane & 15);
                    int c = s * 16 + (lane >> 4) * 8;
                    ldm_x4(smem_u32(&AS[stage * AS_STAGE + r * AS_STRIDE + c]),
                           afrag[mi][0], afrag[mi][1], afrag[mi][2], afrag[mi][3]);
                }
                uint32_t bfrag[8][2];
                #pragma unroll
                for (int njp = 0; njp < 4; njp++) {
                    int g = lane >> 3;
                    int nrow = wn + njp * 16 + (g >> 1) * 8 + (lane & 7);
                    int c = ks * 16 + (g & 1) * 8;
                    uint32_t r0, r1, r2, r3;
                    ldm_x4(smem_u32(&WhS[nrow * 520 + c]), r0, r1, r2, r3);
                    bfrag[njp * 2][0] = r0; bfrag[njp * 2][1] = r1;
                    bfrag[njp * 2 + 1][0] = r2; bfrag[njp * 2 + 1][1] = r3;
                }
                #pragma unroll
                for (int mi = 0; mi < 2; mi++)
                    #pragma unroll
                    for (int ni = 0; ni < 8; ni++)
                        mma16816(acc[mi][ni], afrag[mi], bfrag[ni]);
            }
            // no trailing sync: next chunk's leading sync provides the ordering
        }

        // ---- fused LSTM epilogue (xpS arrived with chunk 0) ----
        const int hlq = (lane & 3) >> 1;
        const int rbase = wm + (lane >> 2);
        #pragma unroll
        for (int mi = 0; mi < 2; mi++) {
            #pragma unroll
            for (int hr = 0; hr < 2; hr++) {
                const int rl = rbase + mi * 16 + hr * 8;
                #pragma unroll
                for (int ni = 0; ni < 8; ni++) {
                    float v0 = acc[mi][ni][hr * 2 + 0];
                    float v1 = acc[mi][ni][hr * 2 + 1];
                    float w0 = __shfl_xor_sync(0xffffffffu, v0, 1);
                    float w1 = __shfl_xor_sync(0xffffffffu, v1, 1);
                    if ((lane & 1) == 0) {
                        const int hl = ((wn + ni * 8) >> 2) + hlq;
                        float gi = v0 + bsS[hl * 4 + 0];
                        float gf = v1 + bsS[hl * 4 + 1];
                        float gg = w0 + bsS[hl * 4 + 2];
                        float go = w1 + bsS[hl * 4 + 3];
                        if (t < szS[rl]) {
                            uint2 xv = *reinterpret_cast<const uint2*>(&xpS[rl * 128 + hl * 4]);
                            __half2 x01 = *reinterpret_cast<__half2*>(&xv.x);
                            __half2 x23 = *reinterpret_cast<__half2*>(&xv.y);
                            gi += __half2float(x01.x);
                            gf += __half2float(x01.y);
                            gg += __half2float(x23.x);
                            go += __half2float(x23.y);
                        }
                        float is = 1.f / (1.f + __expf(-gi));
                        float fs = 1.f / (1.f + __expf(-gf));
                        float gt = tanhf(gg);
                        float os = 1.f / (1.f + __expf(-go));
                        float cn = fs * creg[mi][hr][ni] + is * gt;
                        creg[mi][hr][ni] = cn;
                        hS[rl * 32 + hl] = __float2half(os * tanhf(cn));
                    }
                }
            }
        }
        __syncthreads();
        // coalesced h store: 128 rows x 32 hids
        for (int i = tid; i < 512; i += 256) {
            int r = i >> 2, ch = i & 3;
            *reinterpret_cast<uint4*>(hN + (size_t)(m0 + r) * HID + nblk * 32 + ch * 8) =
                *reinterpret_cast<const uint4*>(&hS[r * 32 + ch * 8]);
        }
        if (t == MAXLEN - 1) break;

        // xp(t+1) prefetch BEFORE the barrier (independent of h)
        for (int i = tid; i < 2048; i += 256) {
            int rl = i >> 4, ch = i & 15;
            bool pv = (t + 1) < szS[rl];
            cp_async16(&xpS[rl * 128 + ch * 8],
                       xp + (size_t)(stS[rl] + t + 1) * GATES + n0 + ch * 8, pv);
        }
        cp_commit();

        group_sync(mblk);

        // A chunk 0 of step t+1 (hN just published by the group)
        for (int i = tid; i < 1024; i += 256) {
            int r = i >> 3, ch = i & 7;
            cp_async16(&AS[r * AS_STRIDE + ch * 8], hN + (size_t)(m0 + r) * HID + ch * 8, true);
        }
        cp_commit();
    }
}

// ---------------------------------------------------------------------------
// fp32 tail GEMM + decoder
// ---------------------------------------------------------------------------
#define BM 64
#define BN 64
#define BK 16
__global__ __launch_bounds__(256) void gemm_nt_kernel(
    const float* __restrict__ A, const float* __restrict__ B,
    const float* __restrict__ bias, const float* __restrict__ R,
    float* __restrict__ C, int M, int N, int K)
{
    __shared__ float As[BK][BM];
    __shared__ float Bs[BK][BN];
    const int m0 = blockIdx.y * BM;
    const int n0 = blockIdx.x * BN;
    const int tid = threadIdx.x;
    const int tx = tid & 15, ty = tid >> 4;
    const int lrow = tid >> 2, lkq = (tid & 3) * 4;
    float acc[4][4] = {};
    for (int k0 = 0; k0 < K; k0 += BK) {
        {
            int gm = m0 + lrow;
            float4 v = make_float4(0.f, 0.f, 0.f, 0.f);
            if (gm < M) v = *reinterpret_cast<const float4*>(A + (size_t)gm * K + k0 + lkq);
            As[lkq + 0][lrow] = v.x; As[lkq + 1][lrow] = v.y;
            As[lkq + 2][lrow] = v.z; As[lkq + 3][lrow] = v.w;
        }
        {
            float4 v = *reinterpret_cast<const float4*>(B + (size_t)(n0 + lrow) * K + k0 + lkq);
            Bs[lkq + 0][lrow] = v.x; Bs[lkq + 1][lrow] = v.y;
            Bs[lkq + 2][lrow] = v.z; Bs[lkq + 3][lrow] = v.w;
        }
        __syncthreads();
        #pragma unroll
        for (int k = 0; k < BK; k++) {
            float4 a = *reinterpret_cast<const float4*>(&As[k][ty * 4]);
            float4 b = *reinterpret_cast<const float4*>(&Bs[k][tx * 4]);
            acc[0][0] += a.x * b.x; acc[0][1] += a.x * b.y; acc[0][2] += a.x * b.z; acc[0][3] += a.x * b.w;
            acc[1][0] += a.y * b.x; acc[1][1] += a.y * b.y; acc[1][2] += a.y * b.z; acc[1][3] += a.y * b.w;
            acc[2][0] += a.z * b.x; acc[2][1] += a.z * b.y; acc[2][2] += a.z * b.z; acc[2][3] += a.z * b.w;
            acc[3][0] += a.w * b.x; acc[3][1] += a.w * b.y; acc[3][2] += a.w * b.z; acc[3][3] += a.w * b.w;
        }
        __syncthreads();
    }
    #pragma unroll
    for (int i = 0; i < 4; i++) {
        int gm = m0 + ty * 4 + i;
        if (gm >= M) continue;
        #pragma unroll
        for (int j = 0; j < 4; j++) {
            int gn = n0 + tx * 4 + j;
            float v = acc[i][j] + bias[gn];
            v = fmaxf(v, 0.f);
            v += R[(size_t)gm * N + gn];
            C[(size_t)gm * N + gn] = v;
        }
    }
}

__global__ void decoder_kernel(const float* __restrict__ X, const float* __restrict__ Wd,
                               const float* __restrict__ bd, float* __restrict__ out, int B)
{
    int warp = (blockIdx.x * blockDim.x + threadIdx.x) >> 5;
    int lane = threadIdx.x & 31;
    if (warp >= B) return;
    const float4* row = reinterpret_cast<const float4*>(X + (size_t)warp * HID);
    const float4* w = reinterpret_cast<const float4*>(Wd);
    float s = 0.f;
    #pragma unroll
    for (int i = lane; i < HID / 4; i += 32) {
        float4 a = row[i], bw = w[i];
        s += a.x * bw.x + a.y * bw.y + a.z * bw.z + a.w * bw.w;
    }
    #pragma unroll
    for (int o = 16; o > 0; o >>= 1) s += __shfl_down_sync(0xffffffffu, s, o);
    if (lane == 0) out[warp] = s + bd[0];
}

// ---------------------------------------------------------------------------
// Launch
// ---------------------------------------------------------------------------
extern "C" void kernel_launch(void* const* d_in, const int* in_sizes, int n_in,
                              void* d_out, int out_size)
{
    const int*   sizes = (const int*)  d_in[0];
    const float* feat  = (const float*)d_in[1];
    const float* We0   = (const float*)d_in[2];
    const float* be0   = (const float*)d_in[3];
    const float* We1   = (const float*)d_in[4];
    const float* be1   = (const float*)d_in[5];
    const float* Wih   = (const float*)d_in[6];
    const float* bih   = (const float*)d_in[7];
    const float* Whh   = (const float*)d_in[8];
    const float* bhh   = (const float*)d_in[9];
    const float* Wl0   = (const float*)d_in[10];
    const float* bl0   = (const float*)d_in[11];
    const float* Wl1   = (const float*)d_in[12];
    const float* bl1   = (const float*)d_in[13];
    const float* Wd    = (const float*)d_in[14];
    const float* bd    = (const float*)d_in[15];

    const int B  = in_sizes[0];
    const int K0 = in_sizes[2] / HID;
    const int T  = in_sizes[1] / K0;

    __half *feat16, *x1h, *x2h, *xp16, *We0h, *We1h, *Wihp, *Whhp, *h0, *h1;
    float *bsum, *hf, *t0, *t1;
    int *starts;
    cudaGetSymbolAddress((void**)&feat16, g_feat16);
    cudaGetSymbolAddress((void**)&x1h,   g_x1h);
    cudaGetSymbolAddress((void**)&x2h,   g_x2h);
    cudaGetSymbolAddress((void**)&xp16,  g_xp16);
    cudaGetSymbolAddress((void**)&We0h,  g_We0h);
    cudaGetSymbolAddress((void**)&We1h,  g_We1h);
    cudaGetSymbolAddress((void**)&Wihp,  g_Wihp);
    cudaGetSymbolAddress((void**)&Whhp,  g_Whhp);
    cudaGetSymbolAddress((void**)&bsum,  g_bsum);
    cudaGetSymbolAddress((void**)&h0,    g_h0);
    cudaGetSymbolAddress((void**)&h1,    g_h1);
    cudaGetSymbolAddress((void**)&hf,    g_hf);
    cudaGetSymbolAddress((void**)&t0,    g_t0);
    cudaGetSymbolAddress((void**)&t1,    g_t1);
    cudaGetSymbolAddress((void**)&starts, g_starts);

    cudaFuncSetAttribute(lstm_persist, cudaFuncAttributeMaxDynamicSharedMemorySize, LSTM_SMEM);

    // launch 1: starts scan
    scan_starts_kernel<<<1, BMAX>>>(sizes, starts, B);

    // launch 2: all conversions / permutations / fills, merged
    const int nb_feat = (T * K0PAD + 255) / 256;
    const int prep_blocks = nb_feat + 384 + 1024 + 4096 + 4096 + 8 + 2048;
    prep_kernel<<<prep_blocks, 256>>>(feat, We0, We1, Wih, Whh, bih, bhh, T, K0, nb_feat);

    // launches 3-5: encoder + xproj
    const int mblkT = (T + 127) / 128;
    hgemm_nt<true, true><<<dim3(HID / 128, mblkT), 256>>>(feat16, We0h, be0, x1h, T, HID, K0PAD);
    hgemm_nt<true, true><<<dim3(HID / 128, mblkT), 256>>>(x1h, We1h, be1, x2h, T, HID, HID);
    hgemm_nt<false, false><<<dim3(GATES / 128, mblkT), 256>>>(x2h, Wihp, nullptr, xp16, T, GATES, HID);

    // launch 6 (ncu -s 5 -c 1 captures this one): persistent LSTM
    lstm_persist<<<NCTA, 256, LSTM_SMEM>>>(Whhp, xp16, bsum, starts, sizes, h0, h1);

    // tail
    h2f_kernel<<<(B * HID + 255) / 256, 256>>>(h0, hf, B * HID);
    gemm_nt_kernel<<<dim3(HID / BN, B / BM), 256>>>(hf, Wl0, bl0, hf, t0, B, HID, HID);
    gemm_nt_kernel<<<dim3(HID / BN, B / BM), 256>>>(t0, Wl1, bl1, t0, t1, B, HID, HID);
    decoder_kernel<<<(B * 32 + 255) / 256, 256>>>(t1, Wd, bd, (float*)d_out, B);
}

// round 8
// speedup vs baseline: 5.1029x; 1.0535x over previous
#include <cuda_runtime.h>
#include <cuda_fp16.h>
#include <math.h>
#include <stdint.h>

// ---------------------------------------------------------------------------
// Problem constants
// ---------------------------------------------------------------------------
#define HID    512
#define GATES  2048
#define MAXLEN 128
#define BMAX   1024
#define TMAX   (BMAX * 127)
#define K0PAD  192
#define NCTA   128         // persistent LSTM grid (16 nblk x 8 mblk)
#define NGRP   8
#define GRPSZ  16

// LSTM kernel chunking
#define CH        64
#define NKT       8
#define AS_STRIDE 72
#define AS_STAGE  (128 * AS_STRIDE)

// hgemm chunking (64-col K chunks, 2 stages)
#define HG_STRIDE 72
#define HG_STAGE  (128 * HG_STRIDE)          // halves per stage
#define HG_SMEM   (4 * HG_STAGE * 2)         // bytes: As[2] + Bs[2]

// ---------------------------------------------------------------------------
// Scratch
// ---------------------------------------------------------------------------
__device__ __half g_feat16[(size_t)TMAX * K0PAD];
__device__ __half g_x1h  [(size_t)TMAX * HID];
__device__ __half g_x2h  [(size_t)TMAX * HID];
__device__ __half g_xp16 [(size_t)TMAX * GATES];
__device__ __half g_We0h [HID * K0PAD];
__device__ __half g_We1h [HID * HID];
__device__ __half g_Wihp [GATES * HID];     // gate-interleaved rows
__device__ __half g_Whhp [GATES * HID];     // gate-interleaved rows
__device__ float  g_bsum [GATES];           // gate-interleaved bih+bhh
__device__ __half g_h0   [BMAX * HID];
__device__ __half g_h1   [BMAX * HID];
__device__ float  g_hf   [BMAX * HID];
__device__ float  g_t0   [BMAX * HID];
__device__ float  g_t1   [BMAX * HID];
__device__ int    g_starts[BMAX];
__device__ unsigned          g_cnt8[NGRP][32];
__device__ volatile unsigned g_gen8[NGRP][32];

// ---------------------------------------------------------------------------
// Helpers
// ---------------------------------------------------------------------------
__device__ __forceinline__ uint32_t smem_u32(const void* p) {
    return (uint32_t)__cvta_generic_to_shared(p);
}
__device__ __forceinline__ void cp_async16(void* dst, const void* src, bool pred) {
    uint32_t d = smem_u32(dst);
    int sz = pred ? 16 : 0;
    asm volatile("cp.async.cg.shared.global [%0], [%1], 16, %2;\n"
                 :: "r"(d), "l"(src), "r"(sz));
}
__device__ __forceinline__ void cp_commit() { asm volatile("cp.async.commit_group;\n"); }
template<int N> __device__ __forceinline__ void cp_wait() {
    asm volatile("cp.async.wait_group %0;\n" :: "n"(N));
}
__device__ __forceinline__ void ldm_x4(uint32_t addr, uint32_t& r0, uint32_t& r1,
                                       uint32_t& r2, uint32_t& r3) {
    asm volatile("ldmatrix.sync.aligned.m8n8.x4.shared.b16 {%0,%1,%2,%3}, [%4];"
                 : "=r"(r0), "=r"(r1), "=r"(r2), "=r"(r3) : "r"(addr));
}
__device__ __forceinline__ void mma16816(float* c, const uint32_t* a, const uint32_t* b) {
    asm volatile("mma.sync.aligned.m16n8k16.row.col.f32.f16.f16.f32 "
                 "{%0,%1,%2,%3}, {%4,%5,%6,%7}, {%8,%9}, {%0,%1,%2,%3};"
                 : "+f"(c[0]), "+f"(c[1]), "+f"(c[2]), "+f"(c[3])
                 : "r"(a[0]), "r"(a[1]), "r"(a[2]), "r"(a[3]), "r"(b[0]), "r"(b[1]));
}

// ---------------------------------------------------------------------------
// setup: scan (launch 1) + merged prep (launch 2)
// ---------------------------------------------------------------------------
__global__ void scan_starts_kernel(const int* __restrict__ sizes, int* __restrict__ starts, int B) {
    __shared__ int s[BMAX];
    int tid = threadIdx.x;
    if (tid < B) s[tid] = sizes[tid];
    __syncthreads();
    if (tid == 0) {
        int acc = 0;
        for (int i = 0; i < B; i++) { starts[i] = acc; acc += s[i]; }
    }
}

__global__ void prep_kernel(const float* __restrict__ feat,
                            const float* __restrict__ We0, const float* __restrict__ We1,
                            const float* __restrict__ Wih, const float* __restrict__ Whh,
                            const float* __restrict__ bih, const float* __restrict__ bhh,
                            int T, int K0, int nb_feat)
{
    int b = blockIdx.x, tid = threadIdx.x;
    if (b < nb_feat) {
        int i = b * 256 + tid;
        if (i < T * K0PAD) {
            int r = i / K0PAD, c = i - r * K0PAD;
            g_feat16[i] = __float2half(c < K0 ? feat[(size_t)r * K0 + c] : 0.f);
        }
        return;
    }
    b -= nb_feat;
    if (b < 384) {
        int i = b * 256 + tid;
        int r = i / K0PAD, c = i - r * K0PAD;
        g_We0h[i] = __float2half(c < K0 ? We0[(size_t)r * K0 + c] : 0.f);
        return;
    }
    b -= 384;
    if (b < 1024) {
        int i = b * 256 + tid;
        g_We1h[i] = __float2half(We1[i]);
        return;
    }
    b -= 1024;
    if (b < 4096) {
        int i = b * 256 + tid;
        int r = i >> 9, c = i & 511;
        int g = r >> 9, hid = r & 511;
        g_Wihp[(size_t)(hid * 4 + g) * HID + c] = __float2half(Wih[i]);
        return;
    }
    b -= 4096;
    if (b < 4096) {
        int i = b * 256 + tid;
        int r = i >> 9, c = i & 511;
        int g = r >> 9, hid = r & 511;
        g_Whhp[(size_t)(hid * 4 + g) * HID + c] = __float2half(Whh[i]);
        return;
    }
    b -= 4096;
    if (b < 8) {
        int o = b * 256 + tid;
        int hid = o >> 2, g = o & 3;
        g_bsum[o] = bih[g * HID + hid] + bhh[g * HID + hid];
        return;
    }
    b -= 8;
    {
        int i = b * 256 + tid;
        g_h0[i] = __float2half(0.f);
    }
}

__global__ void h2f_kernel(const __half* __restrict__ src, float* __restrict__ dst, int n) {
    int i = blockIdx.x * blockDim.x + threadIdx.x;
    if (i < n) dst[i] = __half2float(src[i]);
}

// ---------------------------------------------------------------------------
// fp16 NT GEMM (encoder / xproj): 64-col K chunks, ONE sync per chunk,
// 2-stage cp.async ring, 2 CTAs/SM. K multiple of 64, N multiple of 128.
// ---------------------------------------------------------------------------
template<bool RELU, bool HAS_BIAS>
__global__ __launch_bounds__(256, 2)
void hgemm_nt(const __half* __restrict__ A, const __half* __restrict__ B,
              const float* __restrict__ bias, __half* __restrict__ Cout,
              int M, int N, int K)
{
    extern __shared__ char smem[];
    __half* As = (__half*)smem;                       // [2][128][72]
    __half* Bs = (__half*)(smem + 2 * HG_STAGE * 2);  // [2][128][72]

    const int m0 = blockIdx.y * 128;
    const int n0 = blockIdx.x * 128;
    const int tid = threadIdx.x;
    const int warp = tid >> 5, lane = tid & 31;
    const int wm = (warp & 3) * 32;
    const int wn = (warp >> 2) * 64;

    float acc[2][8][4];
    #pragma unroll
    for (int i = 0; i < 2; i++)
        #pragma unroll
        for (int j = 0; j < 8; j++)
            #pragma unroll
            for (int q = 0; q < 4; q++) acc[i][j][q] = 0.f;

    const int KT = K >> 6;

    // prologue: chunk 0 -> stage 0
    {
        for (int i = tid; i < 1024; i += 256) {
            int r = i >> 3, ch = i & 7;
            int gm = m0 + r;
            bool p = gm < M;
            cp_async16(&As[r * HG_STRIDE + ch * 8], A + (size_t)(p ? gm : 0) * K + ch * 8, p);
        }
        for (int i = tid; i < 1024; i += 256) {
            int r = i >> 3, ch = i & 7;
            cp_async16(&Bs[r * HG_STRIDE + ch * 8], B + (size_t)(n0 + r) * K + ch * 8, true);
        }
        cp_commit();
    }

    for (int kt = 0; kt < KT; kt++) {
        cp_wait<0>();
        __syncthreads();   // stage kt&1 published; all warps done with stage (kt-1)&1
        if (kt + 1 < KT) {
            const int k0 = (kt + 1) << 6;
            const int stg = (kt + 1) & 1;
            for (int i = tid; i < 1024; i += 256) {
                int r = i >> 3, ch = i & 7;
                int gm = m0 + r;
                bool p = gm < M;
                cp_async16(&As[stg * HG_STAGE + r * HG_STRIDE + ch * 8],
                           A + (size_t)(p ? gm : 0) * K + k0 + ch * 8, p);
            }
            for (int i = tid; i < 1024; i += 256) {
                int r = i >> 3, ch = i & 7;
                cp_async16(&Bs[stg * HG_STAGE + r * HG_STRIDE + ch * 8],
                           B + (size_t)(n0 + r) * K + k0 + ch * 8, true);
            }
            cp_commit();
        }
        const int stage = kt & 1;
        #pragma unroll
        for (int s = 0; s < 4; s++) {
            uint32_t afrag[2][4];
            #pragma unroll
            for (int mi = 0; mi < 2; mi++) {
                int r = wm + mi * 16 + (lane & 15);
                int c = s * 16 + (lane >> 4) * 8;
                ldm_x4(smem_u32(&As[stage * HG_STAGE + r * HG_STRIDE + c]),
                       afrag[mi][0], afrag[mi][1], afrag[mi][2], afrag[mi][3]);
            }
            uint32_t bfrag[8][2];
            #pragma unroll
            for (int njp = 0; njp < 4; njp++) {
                int g = lane >> 3;
                int nrow = wn + njp * 16 + (g >> 1) * 8 + (lane & 7);
                int c = s * 16 + (g & 1) * 8;
                uint32_t r0, r1, r2, r3;
                ldm_x4(smem_u32(&Bs[stage * HG_STAGE + nrow * HG_STRIDE + c]), r0, r1, r2, r3);
                bfrag[njp * 2][0] = r0; bfrag[njp * 2][1] = r1;
                bfrag[njp * 2 + 1][0] = r2; bfrag[njp * 2 + 1][1] = r3;
            }
            #pragma unroll
            for (int mi = 0; mi < 2; mi++)
                #pragma unroll
                for (int ni = 0; ni < 8; ni++)
                    mma16816(acc[mi][ni], afrag[mi], bfrag[ni]);
        }
        // no trailing sync: next chunk's leading sync provides ordering
    }

    const int r_lo = lane >> 2;
    const int cpair = (lane & 3) * 2;
    #pragma unroll
    for (int mi = 0; mi < 2; mi++) {
        #pragma unroll
        for (int hr = 0; hr < 2; hr++) {
            int gr = m0 + wm + mi * 16 + r_lo + hr * 8;
            if (gr >= M) continue;
            #pragma unroll
            for (int ni = 0; ni < 8; ni++) {
                int gc = n0 + wn + ni * 8 + cpair;
                float v0 = acc[mi][ni][hr * 2 + 0];
                float v1 = acc[mi][ni][hr * 2 + 1];
                if (HAS_BIAS) { v0 += bias[gc]; v1 += bias[gc + 1]; }
                if (RELU) { v0 = fmaxf(v0, 0.f); v1 = fmaxf(v1, 0.f); }
                __half2 hv;
                hv.x = __float2half(v0); hv.y = __float2half(v1);
                *reinterpret_cast<__half2*>(Cout + (size_t)gr * N + gc) = hv;
            }
        }
    }
}

// ---------------------------------------------------------------------------
// Persistent LSTM (unchanged from round 7)
// ---------------------------------------------------------------------------
#define LSTM_SMEM 212480

__device__ __forceinline__ void group_sync(int grp) {
    __syncthreads();
    if (threadIdx.x == 0) {
        __threadfence();
        unsigned gen = g_gen8[grp][0];
        if (atomicAdd(&g_cnt8[grp][0], 1) == GRPSZ - 1) {
            g_cnt8[grp][0] = 0;
            __threadfence();
            g_gen8[grp][0] = gen + 1;
        } else {
            while (g_gen8[grp][0] == gen) { }
        }
    }
    __syncthreads();
}

__global__ __launch_bounds__(256, 1)
void lstm_persist(const __half* __restrict__ Whp, const __half* __restrict__ xp,
                  const float* __restrict__ bsum,
                  const int* __restrict__ starts, const int* __restrict__ sizes,
                  __half* __restrict__ hbuf0, __half* __restrict__ hbuf1)
{
    extern __shared__ char smem[];
    __half* WhS = (__half*)(smem);
    __half* AS  = (__half*)(smem + 133120);
    __half* xpS = (__half*)(smem + 169984);
    float*  bsS = (float*) (smem + 202752);
    int*    stS = (int*)   (smem + 203264);
    int*    szS = (int*)   (smem + 203776);
    __half* hS  = (__half*)(smem + 204288);

    const int tid  = threadIdx.x;
    const int warp = tid >> 5, lane = tid & 31;
    const int nblk = blockIdx.x & 15, mblk = blockIdx.x >> 4;
    const int n0 = nblk * 128, m0 = mblk * 128;
    const int wm = (warp & 3) * 32, wn = (warp >> 2) * 64;

    for (int i = tid; i < 128 * 64; i += 256) {
        int r = i >> 6, ch = i & 63;
        cp_async16(&WhS[r * 520 + ch * 8], Whp + (size_t)(n0 + r) * HID + ch * 8, true);
    }
    cp_commit();
    for (int i = tid; i < 128; i += 256) {
        bsS[i] = bsum[n0 + i];
        stS[i] = starts[m0 + i];
        szS[i] = sizes[m0 + i];
    }
    cp_wait<0>();
    __syncthreads();

    float creg[2][2][8];
    #pragma unroll
    for (int mi = 0; mi < 2; mi++)
        #pragma unroll
        for (int hr = 0; hr < 2; hr++)
            #pragma unroll
            for (int ni = 0; ni < 8; ni++) creg[mi][hr][ni] = 0.f;

    for (int i = tid; i < 2048; i += 256) {
        int rl = i >> 4, ch = i & 15;
        bool pv = 0 < szS[rl];
        cp_async16(&xpS[rl * 128 + ch * 8], xp + (size_t)stS[rl] * GATES + n0 + ch * 8, pv);
    }
    for (int i = tid; i < 1024; i += 256) {
        int r = i >> 3, ch = i & 7;
        cp_async16(&AS[r * AS_STRIDE + ch * 8], hbuf0 + (size_t)(m0 + r) * HID + ch * 8, true);
    }
    cp_commit();

    for (int t = 0; t < MAXLEN; t++) {
        const __half* hA = (t & 1) ? hbuf1 : hbuf0;
        __half*       hN = (t & 1) ? hbuf0 : hbuf1;

        float acc[2][8][4];
        #pragma unroll
        for (int mi = 0; mi < 2; mi++)
            #pragma unroll
            for (int ni = 0; ni < 8; ni++)
                #pragma unroll
                for (int q = 0; q < 4; q++) acc[mi][ni][q] = 0.f;

        for (int kt = 0; kt < NKT; kt++) {
            cp_wait<0>();
            __syncthreads();
            if (kt < NKT - 1) {
                const int k0 = (kt + 1) * CH;
                const int stg = (kt + 1) & 1;
                for (int i = tid; i < 1024; i += 256) {
                    int r = i >> 3, ch = i & 7;
                    cp_async16(&AS[stg * AS_STAGE + r * AS_STRIDE + ch * 8],
                               hA + (size_t)(m0 + r) * HID + k0 + ch * 8, true);
                }
                cp_commit();
            }
            const int stage = kt & 1;
            #pragma unroll
            for (int s = 0; s < 4; s++) {
                const int ks = kt * 4 + s;
                uint32_t afrag[2][4];
                #pragma unroll
                for (int mi = 0; mi < 2; mi++) {
                    int r = wm + mi * 16 + (lane & 15);
                    int c = s * 16 + (lane >> 4) * 8;
                    ldm_x4(smem_u32(&AS[stage * AS_STAGE + r * AS_STRIDE + c]),
                           afrag[mi][0], afrag[mi][1], afrag[mi][2], afrag[mi][3]);
                }
                uint32_t bfrag[8][2];
                #pragma unroll
                for (int njp = 0; njp < 4; njp++) {
                    int g = lane >> 3;
                    int nrow = wn + njp * 16 + (g >> 1) * 8 + (lane & 7);
                    int c = ks * 16 + (g & 1) * 8;
                    uint32_t r0, r1, r2, r3;
                    ldm_x4(smem_u32(&WhS[nrow * 520 + c]), r0, r1, r2, r3);
                    bfrag[njp * 2][0] = r0; bfrag[njp * 2][1] = r1;
                    bfrag[njp * 2 + 1][0] = r2; bfrag[njp * 2 + 1][1] = r3;
                }
                #pragma unroll
                for (int mi = 0; mi < 2; mi++)
                    #pragma unroll
                    for (int ni = 0; ni < 8; ni++)
                        mma16816(acc[mi][ni], afrag[mi], bfrag[ni]);
            }
        }

        const int hlq = (lane & 3) >> 1;
        const int rbase = wm + (lane >> 2);
        #pragma unroll
        for (int mi = 0; mi < 2; mi++) {
            #pragma unroll
            for (int hr = 0; hr < 2; hr++) {
                const int rl = rbase + mi * 16 + hr * 8;
                #pragma unroll
                for (int ni = 0; ni < 8; ni++) {
                    float v0 = acc[mi][ni][hr * 2 + 0];
                    float v1 = acc[mi][ni][hr * 2 + 1];
                    float w0 = __shfl_xor_sync(0xffffffffu, v0, 1);
                    float w1 = __shfl_xor_sync(0xffffffffu, v1, 1);
                    if ((lane & 1) == 0) {
                        const int hl = ((wn + ni * 8) >> 2) + hlq;
                        float gi = v0 + bsS[hl * 4 + 0];
                        float gf = v1 + bsS[hl * 4 + 1];
                        float gg = w0 + bsS[hl * 4 + 2];
                        float go = w1 + bsS[hl * 4 + 3];
                        if (t < szS[rl]) {
                            uint2 xv = *reinterpret_cast<const uint2*>(&xpS[rl * 128 + hl * 4]);
                            __half2 x01 = *reinterpret_cast<__half2*>(&xv.x);
                            __half2 x23 = *reinterpret_cast<__half2*>(&xv.y);
                            gi += __half2float(x01.x);
                            gf += __half2float(x01.y);
                            gg += __half2float(x23.x);
                            go += __half2float(x23.y);
                        }
                        float is = 1.f / (1.f + __expf(-gi));
                        float fs = 1.f / (1.f + __expf(-gf));
                        float gt = tanhf(gg);
                        float os = 1.f / (1.f + __expf(-go));
                        float cn = fs * creg[mi][hr][ni] + is * gt;
                        creg[mi][hr][ni] = cn;
                        hS[rl * 32 + hl] = __float2half(os * tanhf(cn));
                    }
                }
            }
        }
        __syncthreads();
        for (int i = tid; i < 512; i += 256) {
            int r = i >> 2, ch = i & 3;
            *reinterpret_cast<uint4*>(hN + (size_t)(m0 + r) * HID + nblk * 32 + ch * 8) =
                *reinterpret_cast<const uint4*>(&hS[r * 32 + ch * 8]);
        }
        if (t == MAXLEN - 1) break;

        for (int i = tid; i < 2048; i += 256) {
            int rl = i >> 4, ch = i & 15;
            bool pv = (t + 1) < szS[rl];
            cp_async16(&xpS[rl * 128 + ch * 8],
                       xp + (size_t)(stS[rl] + t + 1) * GATES + n0 + ch * 8, pv);
        }
        cp_commit();

        group_sync(mblk);

        for (int i = tid; i < 1024; i += 256) {
            int r = i >> 3, ch = i & 7;
            cp_async16(&AS[r * AS_STRIDE + ch * 8], hN + (size_t)(m0 + r) * HID + ch * 8, true);
        }
        cp_commit();
    }
}

// ---------------------------------------------------------------------------
// fp32 tail GEMM + decoder
// ---------------------------------------------------------------------------
#define BM 64
#define BN 64
#define BK 16
__global__ __launch_bounds__(256) void gemm_nt_kernel(
    const float* __restrict__ A, const float* __restrict__ B,
    const float* __restrict__ bias, const float* __restrict__ R,
    float* __restrict__ C, int M, int N, int K)
{
    __shared__ float As[BK][BM];
    __shared__ float Bs[BK][BN];
    const int m0 = blockIdx.y * BM;
    const int n0 = blockIdx.x * BN;
    const int tid = threadIdx.x;
    const int tx = tid & 15, ty = tid >> 4;
    const int lrow = tid >> 2, lkq = (tid & 3) * 4;
    float acc[4][4] = {};
    for (int k0 = 0; k0 < K; k0 += BK) {
        {
            int gm = m0 + lrow;
            float4 v = make_float4(0.f, 0.f, 0.f, 0.f);
            if (gm < M) v = *reinterpret_cast<const float4*>(A + (size_t)gm * K + k0 + lkq);
            As[lkq + 0][lrow] = v.x; As[lkq + 1][lrow] = v.y;
            As[lkq + 2][lrow] = v.z; As[lkq + 3][lrow] = v.w;
        }
        {
            float4 v = *reinterpret_cast<const float4*>(B + (size_t)(n0 + lrow) * K + k0 + lkq);
            Bs[lkq + 0][lrow] = v.x; Bs[lkq + 1][lrow] = v.y;
            Bs[lkq + 2][lrow] = v.z; Bs[lkq + 3][lrow] = v.w;
        }
        __syncthreads();
        #pragma unroll
        for (int k = 0; k < BK; k++) {
            float4 a = *reinterpret_cast<const float4*>(&As[k][ty * 4]);
            float4 b = *reinterpret_cast<const float4*>(&Bs[k][tx * 4]);
            acc[0][0] += a.x * b.x; acc[0][1] += a.x * b.y; acc[0][2] += a.x * b.z; acc[0][3] += a.x * b.w;
            acc[1][0] += a.y * b.x; acc[1][1] += a.y * b.y; acc[1][2] += a.y * b.z; acc[1][3] += a.y * b.w;
            acc[2][0] += a.z * b.x; acc[2][1] += a.z * b.y; acc[2][2] += a.z * b.z; acc[2][3] += a.z * b.w;
            acc[3][0] += a.w * b.x; acc[3][1] += a.w * b.y; acc[3][2] += a.w * b.z; acc[3][3] += a.w * b.w;
        }
        __syncthreads();
    }
    #pragma unroll
    for (int i = 0; i < 4; i++) {
        int gm = m0 + ty * 4 + i;
        if (gm >= M) continue;
        #pragma unroll
        for (int j = 0; j < 4; j++) {
            int gn = n0 + tx * 4 + j;
            float v = acc[i][j] + bias[gn];
            v = fmaxf(v, 0.f);
            v += R[(size_t)gm * N + gn];
            C[(size_t)gm * N + gn] = v;
        }
    }
}

__global__ void decoder_kernel(const float* __restrict__ X, const float* __restrict__ Wd,
                               const float* __restrict__ bd, float* __restrict__ out, int B)
{
    int warp = (blockIdx.x * blockDim.x + threadIdx.x) >> 5;
    int lane = threadIdx.x & 31;
    if (warp >= B) return;
    const float4* row = reinterpret_cast<const float4*>(X + (size_t)warp * HID);
    const float4* w = reinterpret_cast<const float4*>(Wd);
    float s = 0.f;
    #pragma unroll
    for (int i = lane; i < HID / 4; i += 32) {
        float4 a = row[i], bw = w[i];
        s += a.x * bw.x + a.y * bw.y + a.z * bw.z + a.w * bw.w;
    }
    #pragma unroll
    for (int o = 16; o > 0; o >>= 1) s += __shfl_down_sync(0xffffffffu, s, o);
    if (lane == 0) out[warp] = s + bd[0];
}

// ---------------------------------------------------------------------------
// Launch
// ---------------------------------------------------------------------------
extern "C" void kernel_launch(void* const* d_in, const int* in_sizes, int n_in,
                              void* d_out, int out_size)
{
    const int*   sizes = (const int*)  d_in[0];
    const float* feat  = (const float*)d_in[1];
    const float* We0   = (const float*)d_in[2];
    const float* be0   = (const float*)d_in[3];
    const float* We1   = (const float*)d_in[4];
    const float* be1   = (const float*)d_in[5];
    const float* Wih   = (const float*)d_in[6];
    const float* bih   = (const float*)d_in[7];
    const float* Whh   = (const float*)d_in[8];
    const float* bhh   = (const float*)d_in[9];
    const float* Wl0   = (const float*)d_in[10];
    const float* bl0   = (const float*)d_in[11];
    const float* Wl1   = (const float*)d_in[12];
    const float* bl1   = (const float*)d_in[13];
    const float* Wd    = (const float*)d_in[14];
    const float* bd    = (const float*)d_in[15];

    const int B  = in_sizes[0];
    const int K0 = in_sizes[2] / HID;
    const int T  = in_sizes[1] / K0;

    __half *feat16, *x1h, *x2h, *xp16, *We0h, *We1h, *Wihp, *Whhp, *h0, *h1;
    float *bsum, *hf, *t0, *t1;
    int *starts;
    cudaGetSymbolAddress((void**)&feat16, g_feat16);
    cudaGetSymbolAddress((void**)&x1h,   g_x1h);
    cudaGetSymbolAddress((void**)&x2h,   g_x2h);
    cudaGetSymbolAddress((void**)&xp16,  g_xp16);
    cudaGetSymbolAddress((void**)&We0h,  g_We0h);
    cudaGetSymbolAddress((void**)&We1h,  g_We1h);
    cudaGetSymbolAddress((void**)&Wihp,  g_Wihp);
    cudaGetSymbolAddress((void**)&Whhp,  g_Whhp);
    cudaGetSymbolAddress((void**)&bsum,  g_bsum);
    cudaGetSymbolAddress((void**)&h0,    g_h0);
    cudaGetSymbolAddress((void**)&h1,    g_h1);
    cudaGetSymbolAddress((void**)&hf,    g_hf);
    cudaGetSymbolAddress((void**)&t0,    g_t0);
    cudaGetSymbolAddress((void**)&t1,    g_t1);
    cudaGetSymbolAddress((void**)&starts, g_starts);

    cudaFuncSetAttribute(lstm_persist, cudaFuncAttributeMaxDynamicSharedMemorySize, LSTM_SMEM);
    cudaFuncSetAttribute(hgemm_nt<true, true>,  cudaFuncAttributeMaxDynamicSharedMemorySize, HG_SMEM);
    cudaFuncSetAttribute(hgemm_nt<false, false>, cudaFuncAttributeMaxDynamicSharedMemorySize, HG_SMEM);

    // launch 1: starts scan
    scan_starts_kernel<<<1, BMAX>>>(sizes, starts, B);

    // launch 2: merged prep
    const int nb_feat = (T * K0PAD + 255) / 256;
    const int prep_blocks = nb_feat + 384 + 1024 + 4096 + 4096 + 8 + 2048;
    prep_kernel<<<prep_blocks, 256>>>(feat, We0, We1, Wih, Whh, bih, bhh, T, K0, nb_feat);

    // launches 3-5: encoder + xproj
    const int mblkT = (T + 127) / 128;
    hgemm_nt<true, true><<<dim3(HID / 128, mblkT), 256, HG_SMEM>>>(feat16, We0h, be0, x1h, T, HID, K0PAD);
    hgemm_nt<true, true><<<dim3(HID / 128, mblkT), 256, HG_SMEM>>>(x1h, We1h, be1, x2h, T, HID, HID);
    hgemm_nt<false, false><<<dim3(GATES / 128, mblkT), 256, HG_SMEM>>>(x2h, Wihp, nullptr, xp16, T, GATES, HID);

    // launch 6: persistent LSTM
    lstm_persist<<<NCTA, 256, LSTM_SMEM>>>(Whhp, xp16, bsum, starts, sizes, h0, h1);

    // tail
    h2f_kernel<<<(B * HID + 255) / 256, 256>>>(h0, hf, B * HID);
    gemm_nt_kernel<<<dim3(HID / BN, B / BM), 256>>>(hf, Wl0, bl0, hf, t0, B, HID, HID);
    gemm_nt_kernel<<<dim3(HID / BN, B / BM), 256>>>(t0, Wl1, bl1, t0, t1, B, HID, HID);
    decoder_kernel<<<(B * 32 + 255) / 256, 256>>>(t1, Wd, bd, (float*)d_out, B);
}